// round 5
// baseline (speedup 1.0000x reference)
#include <cuda_runtime.h>
#include <stdint.h>

// Problem dims (fixed by the reference)
#define MQ    8192      // B*S query vectors
#define DD    1024      // feature dim
#define NC    16384     // number of codes
#define KSEL  8         // top-k

// GEMM tiling
#define BM 64
#define BN 128
#define BK 16
#define NT 256

// Module-scope scratch. ONLY referenced from device code (host must never take
// their address -- that was the root cause of the 128 MiB HMM allocations).
__device__ float g_c2[NC];   // per-code squared norms
__device__ float g_x2[MQ];   // per-query squared norms

// ---------------------------------------------------------------------------
// Row squared-norm kernels: one warp per row; write module globals directly.
// ---------------------------------------------------------------------------
__global__ void cnorm_kernel(const float* __restrict__ src) {
    int row = blockIdx.x * 8 + (threadIdx.x >> 5);
    if (row >= NC) return;
    int lane = threadIdx.x & 31;
    const float4* r4 = (const float4*)(src + (size_t)row * DD);
    float s = 0.f;
#pragma unroll
    for (int i = 0; i < 8; ++i) {
        float4 v = r4[i * 32 + lane];
        s += v.x * v.x + v.y * v.y + v.z * v.z + v.w * v.w;
    }
#pragma unroll
    for (int o = 16; o > 0; o >>= 1) s += __shfl_xor_sync(0xffffffffu, s, o);
    if (lane == 0) g_c2[row] = s;
}

__global__ void xnorm_kernel(const float* __restrict__ src) {
    int row = blockIdx.x * 8 + (threadIdx.x >> 5);
    if (row >= MQ) return;
    int lane = threadIdx.x & 31;
    const float4* r4 = (const float4*)(src + (size_t)row * DD);
    float s = 0.f;
#pragma unroll
    for (int i = 0; i < 8; ++i) {
        float4 v = r4[i * 32 + lane];
        s += v.x * v.x + v.y * v.y + v.z * v.z + v.w * v.w;
    }
#pragma unroll
    for (int o = 16; o > 0; o >>= 1) s += __shfl_xor_sync(0xffffffffu, s, o);
    if (lane == 0) g_x2[row] = s;
}

// ---------------------------------------------------------------------------
// Scalar top-8 machinery (no per-thread arrays).
// List sorted: value desc; ties -> smaller index first (matches JAX top_k).
#define BUBBLE(va, ia, vb, ib)                                    \
    if (va > vb || (va == vb && ia < ib)) {                       \
        float _tv = va; va = vb; vb = _tv;                        \
        int   _ti = ia; ia = ib; ib = _ti;                        \
    }

#define TRYINS(s, n)                                              \
    if ((s) > v7 || ((s) == v7 && (n) < j7)) {                    \
        v7 = (s); j7 = (n);                                       \
        BUBBLE(v7, j7, v6, j6)                                    \
        BUBBLE(v6, j6, v5, j5)                                    \
        BUBBLE(v5, j5, v4, j4)                                    \
        BUBBLE(v4, j4, v3, j3)                                    \
        BUBBLE(v3, j3, v2, j2)                                    \
        BUBBLE(v2, j2, v1, j1)                                    \
        BUBBLE(v1, j1, v0, j0)                                    \
    }

#define FMAROW(a, c0, c1, c2, c3, c4, c5, c6, c7)                 \
    c0 = fmaf(a, b0, c0); c1 = fmaf(a, b1, c1);                   \
    c2 = fmaf(a, b2, c2); c3 = fmaf(a, b3, c3);                   \
    c4 = fmaf(a, b4, c4); c5 = fmaf(a, b5, c5);                   \
    c6 = fmaf(a, b6, c6); c7 = fmaf(a, b7, c7);

// logit = -((x2 - 2*xc) + c2), mirroring the reference formula order
#define STG1(c, nOff) (-(fmaf(-2.f, (c), x2r) + g_c2[nBase + tx * 8 + (nOff)]))

__global__ __launch_bounds__(NT, 1)
void fused_topk_kernel(const float* __restrict__ X,     // [MQ, DD]
                       const float* __restrict__ C,     // [NC, DD]
                       float* __restrict__ out,         // [MQ, DD]
                       float* __restrict__ out_ids)     // [MQ,K] as float, or null
{
    __shared__ float As[BK][BM];       // 4 KB
    __shared__ float Bs[BK][BN];       // 8 KB
    __shared__ float Stg[BM * BN];     // 32 KB staging; reused for merge + ids

    const int tid = threadIdx.x;
    const int tx  = tid & 15;          // 16 col-groups of 8
    const int ty  = tid >> 4;          // 16 row-groups of 4
    const int mBase = blockIdx.x * BM;

    const float NEG_INF = __int_as_float(0xff800000);

    float v0 = NEG_INF, v1 = NEG_INF, v2 = NEG_INF, v3 = NEG_INF;
    float v4 = NEG_INF, v5 = NEG_INF, v6 = NEG_INF, v7 = NEG_INF;
    int j0 = 0x7FFFFFFF, j1 = 0x7FFFFFFF, j2 = 0x7FFFFFFF, j3 = 0x7FFFFFFF;
    int j4 = 0x7FFFFFFF, j5 = 0x7FFFFFFF, j6 = 0x7FFFFFFF, j7 = 0x7FFFFFFF;

    const int q_scan = tid >> 2;       // query this thread scans (0..63)
    const int l4     = tid & 3;        // which 32-col slice of the chunk
    const int rot    = (q_scan + l4 * 8) & 31;   // bank-conflict-free rotation

#pragma unroll 1
    for (int chunk = 0; chunk < NC / BN; ++chunk) {
        const int nBase = chunk * BN;

        float c00 = 0.f, c01 = 0.f, c02 = 0.f, c03 = 0.f, c04 = 0.f, c05 = 0.f, c06 = 0.f, c07 = 0.f;
        float c10 = 0.f, c11 = 0.f, c12 = 0.f, c13 = 0.f, c14 = 0.f, c15 = 0.f, c16 = 0.f, c17 = 0.f;
        float c20 = 0.f, c21 = 0.f, c22 = 0.f, c23 = 0.f, c24 = 0.f, c25 = 0.f, c26 = 0.f, c27 = 0.f;
        float c30 = 0.f, c31 = 0.f, c32 = 0.f, c33 = 0.f, c34 = 0.f, c35 = 0.f, c36 = 0.f, c37 = 0.f;

#pragma unroll 1
        for (int kt = 0; kt < DD / BK; ++kt) {
            {
                int r = tid >> 2;
                int c = (tid & 3) << 2;
                float4 v = *(const float4*)(X + (size_t)(mBase + r) * DD + kt * BK + c);
                As[c + 0][r] = v.x; As[c + 1][r] = v.y;
                As[c + 2][r] = v.z; As[c + 3][r] = v.w;
            }
#pragma unroll
            for (int u = 0; u < 2; ++u) {
                int f = tid * 2 + u;
                int n = f >> 2;
                int c = (f & 3) << 2;
                float4 v = *(const float4*)(C + (size_t)(nBase + n) * DD + kt * BK + c);
                Bs[c + 0][n] = v.x; Bs[c + 1][n] = v.y;
                Bs[c + 2][n] = v.z; Bs[c + 3][n] = v.w;
            }
            __syncthreads();

#pragma unroll
            for (int kk = 0; kk < BK; ++kk) {
                float4 av = *(const float4*)&As[kk][ty * 4];
                float4 bl = *(const float4*)&Bs[kk][tx * 8];
                float4 bh = *(const float4*)&Bs[kk][tx * 8 + 4];
                float b0 = bl.x, b1 = bl.y, b2 = bl.z, b3 = bl.w;
                float b4 = bh.x, b5 = bh.y, b6 = bh.z, b7 = bh.w;
                FMAROW(av.x, c00, c01, c02, c03, c04, c05, c06, c07)
                FMAROW(av.y, c10, c11, c12, c13, c14, c15, c16, c17)
                FMAROW(av.z, c20, c21, c22, c23, c24, c25, c26, c27)
                FMAROW(av.w, c30, c31, c32, c33, c34, c35, c36, c37)
            }
            __syncthreads();
        }

        // Stage logits into Stg
        {
            float x2r; float4 s;
            x2r = g_x2[mBase + ty * 4 + 0];
            s.x = STG1(c00, 0); s.y = STG1(c01, 1); s.z = STG1(c02, 2); s.w = STG1(c03, 3);
            *(float4*)&Stg[(ty * 4 + 0) * BN + tx * 8] = s;
            s.x = STG1(c04, 4); s.y = STG1(c05, 5); s.z = STG1(c06, 6); s.w = STG1(c07, 7);
            *(float4*)&Stg[(ty * 4 + 0) * BN + tx * 8 + 4] = s;
            x2r = g_x2[mBase + ty * 4 + 1];
            s.x = STG1(c10, 0); s.y = STG1(c11, 1); s.z = STG1(c12, 2); s.w = STG1(c13, 3);
            *(float4*)&Stg[(ty * 4 + 1) * BN + tx * 8] = s;
            s.x = STG1(c14, 4); s.y = STG1(c15, 5); s.z = STG1(c16, 6); s.w = STG1(c17, 7);
            *(float4*)&Stg[(ty * 4 + 1) * BN + tx * 8 + 4] = s;
            x2r = g_x2[mBase + ty * 4 + 2];
            s.x = STG1(c20, 0); s.y = STG1(c21, 1); s.z = STG1(c22, 2); s.w = STG1(c23, 3);
            *(float4*)&Stg[(ty * 4 + 2) * BN + tx * 8] = s;
            s.x = STG1(c24, 4); s.y = STG1(c25, 5); s.z = STG1(c26, 6); s.w = STG1(c27, 7);
            *(float4*)&Stg[(ty * 4 + 2) * BN + tx * 8 + 4] = s;
            x2r = g_x2[mBase + ty * 4 + 3];
            s.x = STG1(c30, 0); s.y = STG1(c31, 1); s.z = STG1(c32, 2); s.w = STG1(c33, 3);
            *(float4*)&Stg[(ty * 4 + 3) * BN + tx * 8] = s;
            s.x = STG1(c34, 4); s.y = STG1(c35, 5); s.z = STG1(c36, 6); s.w = STG1(c37, 7);
            *(float4*)&Stg[(ty * 4 + 3) * BN + tx * 8 + 4] = s;
        }
        __syncthreads();

        // Top-k scan: 4 threads per query, each scans 32 columns (rotated).
#pragma unroll 1
        for (int j = 0; j < 32; ++j) {
            int jj  = (j + rot) & 31;
            int col = l4 * 32 + jj;
            float s = Stg[q_scan * BN + col];
            int   n = nBase + col;
            TRYINS(s, n)
        }
        __syncthreads();   // protect Stg before next chunk overwrites it
    }

    // ---- Final merge: 4 partial top-8 lists per query -> top-8 --------------
    float* candV = Stg;                          // [64][32]
    int*   candI = (int*)(Stg + BM * 32);        // [64][32]
    int*   idsS  = (int*)(Stg + BM * 64);        // [64][8]

    {
        int base = q_scan * 32 + l4 * 8;
        candV[base + 0] = v0; candI[base + 0] = j0;
        candV[base + 1] = v1; candI[base + 1] = j1;
        candV[base + 2] = v2; candI[base + 2] = j2;
        candV[base + 3] = v3; candI[base + 3] = j3;
        candV[base + 4] = v4; candI[base + 4] = j4;
        candV[base + 5] = v5; candI[base + 5] = j5;
        candV[base + 6] = v6; candI[base + 6] = j6;
        candV[base + 7] = v7; candI[base + 7] = j7;
    }
    __syncthreads();

    if (tid < BM) {
        v0 = v1 = v2 = v3 = v4 = v5 = v6 = v7 = NEG_INF;
        j0 = j1 = j2 = j3 = j4 = j5 = j6 = j7 = 0x7FFFFFFF;
#pragma unroll 1
        for (int j = 0; j < 4 * KSEL; ++j) {
            float s = candV[tid * 32 + j];
            int   n = candI[tid * 32 + j];
            TRYINS(s, n)
        }
        idsS[tid * KSEL + 0] = j0; idsS[tid * KSEL + 1] = j1;
        idsS[tid * KSEL + 2] = j2; idsS[tid * KSEL + 3] = j3;
        idsS[tid * KSEL + 4] = j4; idsS[tid * KSEL + 5] = j5;
        idsS[tid * KSEL + 6] = j6; idsS[tid * KSEL + 7] = j7;
        if (out_ids) {
            float* o = out_ids + (size_t)(mBase + tid) * KSEL;
            o[0] = (float)j0; o[1] = (float)j1; o[2] = (float)j2; o[3] = (float)j3;
            o[4] = (float)j4; o[5] = (float)j5; o[6] = (float)j6; o[7] = (float)j7;
        }
    }
    __syncthreads();

    // ---- Gather + mean epilogue: out[q] = mean of the 8 selected code rows --
#pragma unroll 1
    for (int idx = tid; idx < BM * DD; idx += NT) {
        int q = idx >> 10;        // / DD
        int d = idx & (DD - 1);
        int i0 = idsS[q * KSEL + 0], i1 = idsS[q * KSEL + 1];
        int i2 = idsS[q * KSEL + 2], i3 = idsS[q * KSEL + 3];
        int i4 = idsS[q * KSEL + 4], i5 = idsS[q * KSEL + 5];
        int i6 = idsS[q * KSEL + 6], i7 = idsS[q * KSEL + 7];
        float s = C[(size_t)i0 * DD + d] + C[(size_t)i1 * DD + d]
                + C[(size_t)i2 * DD + d] + C[(size_t)i3 * DD + d]
                + C[(size_t)i4 * DD + d] + C[(size_t)i5 * DD + d]
                + C[(size_t)i6 * DD + d] + C[(size_t)i7 * DD + d];
        out[(size_t)(mBase + q) * DD + d] = s * 0.125f;
    }
}

// ---------------------------------------------------------------------------
extern "C" void kernel_launch(void* const* d_in, const int* in_sizes, int n_in,
                              void* d_out, int out_size)
{
    const float* X = (const float*)d_in[0];   // inputs  [4,2048,1024] f32
    const float* C = (const float*)d_in[1];   // codebook [16384,1024] f32
    // d_in[2] = kcodes (scalar, fixed at 8)

    float* out     = (float*)d_out;
    float* out_ids = nullptr;
    if (out_size >= MQ * DD + MQ * KSEL)
        out_ids = out + (size_t)MQ * DD;      // ids appended after outputs

    cnorm_kernel<<<NC / 8, 256>>>(C);         // writes g_c2 (device-side symbol)
    xnorm_kernel<<<MQ / 8, 256>>>(X);         // writes g_x2 (device-side symbol)
    fused_topk_kernel<<<MQ / BM, NT>>>(X, C, out, out_ids);
}

// round 7
// speedup vs baseline: 5.7800x; 5.7800x over previous
#include <cuda_runtime.h>
#include <cuda_bf16.h>
#include <stdint.h>

// Problem dims (fixed by the reference)
#define MQ    8192      // B*S query vectors
#define DD    1024      // feature dim
#define NC    16384     // number of codes
#define KSEL  8         // top-k
#define NCAND 32        // shortlist size per query (4 threads x top-8)

// Shortlist GEMM tiling
#define BM 64
#define BN 128
#define BK 32
#define NT 256

// ---------------------------------------------------------------------------
// Module-scope device scratch (only ever referenced from device code).
__device__ float            g_c2[NC];          // per-code squared norms
__device__ float            g_x2[MQ];          // per-query squared norms
__device__ __nv_bfloat16    g_Xh[(size_t)MQ * DD];   // bf16 queries   (16 MB)
__device__ __nv_bfloat16    g_Ch[(size_t)NC * DD];   // bf16 codebook  (32 MB)
__device__ int              g_cand[(size_t)MQ * NCAND]; // shortlist ids (1 MB)

// ---------------------------------------------------------------------------
// Norm kernels (one warp per row), writing module globals device-side.
__global__ void cnorm_kernel(const float* __restrict__ src) {
    int row = blockIdx.x * 8 + (threadIdx.x >> 5);
    if (row >= NC) return;
    int lane = threadIdx.x & 31;
    const float4* r4 = (const float4*)(src + (size_t)row * DD);
    float s = 0.f;
#pragma unroll
    for (int i = 0; i < 8; ++i) {
        float4 v = r4[i * 32 + lane];
        s += v.x * v.x + v.y * v.y + v.z * v.z + v.w * v.w;
    }
#pragma unroll
    for (int o = 16; o > 0; o >>= 1) s += __shfl_xor_sync(0xffffffffu, s, o);
    if (lane == 0) g_c2[row] = s;
}

__global__ void xnorm_kernel(const float* __restrict__ src) {
    int row = blockIdx.x * 8 + (threadIdx.x >> 5);
    if (row >= MQ) return;
    int lane = threadIdx.x & 31;
    const float4* r4 = (const float4*)(src + (size_t)row * DD);
    float s = 0.f;
#pragma unroll
    for (int i = 0; i < 8; ++i) {
        float4 v = r4[i * 32 + lane];
        s += v.x * v.x + v.y * v.y + v.z * v.z + v.w * v.w;
    }
#pragma unroll
    for (int o = 16; o > 0; o >>= 1) s += __shfl_xor_sync(0xffffffffu, s, o);
    if (lane == 0) g_x2[row] = s;
}

// ---------------------------------------------------------------------------
// fp32 -> bf16 conversion kernels (4 elements per thread)
__global__ void cvtX_kernel(const float* __restrict__ src) {
    size_t gi = (size_t)blockIdx.x * 256 + threadIdx.x;   // float4 index
    float4 v = ((const float4*)src)[gi];
    __nv_bfloat162* dst = (__nv_bfloat162*)&g_Xh[gi * 4];
    dst[0] = __floats2bfloat162_rn(v.x, v.y);
    dst[1] = __floats2bfloat162_rn(v.z, v.w);
}
__global__ void cvtC_kernel(const float* __restrict__ src) {
    size_t gi = (size_t)blockIdx.x * 256 + threadIdx.x;
    float4 v = ((const float4*)src)[gi];
    __nv_bfloat162* dst = (__nv_bfloat162*)&g_Ch[gi * 4];
    dst[0] = __floats2bfloat162_rn(v.x, v.y);
    dst[1] = __floats2bfloat162_rn(v.z, v.w);
}

// ---------------------------------------------------------------------------
// Scalar top-8 machinery. Sorted: value desc; ties -> smaller index first.
#define BUBBLE(va, ia, vb, ib)                                    \
    if (va > vb || (va == vb && ia < ib)) {                       \
        float _tv = va; va = vb; vb = _tv;                        \
        int   _ti = ia; ia = ib; ib = _ti;                        \
    }

#define TRYINS(s, n)                                              \
    if ((s) > v7 || ((s) == v7 && (n) < j7)) {                    \
        v7 = (s); j7 = (n);                                       \
        BUBBLE(v7, j7, v6, j6)                                    \
        BUBBLE(v6, j6, v5, j5)                                    \
        BUBBLE(v5, j5, v4, j4)                                    \
        BUBBLE(v4, j4, v3, j3)                                    \
        BUBBLE(v3, j3, v2, j2)                                    \
        BUBBLE(v2, j2, v1, j1)                                    \
        BUBBLE(v1, j1, v0, j0)                                    \
    }

// ---------------------------------------------------------------------------
// PTX wrappers
__device__ __forceinline__ void ldsm_x4(uint32_t* r, uint32_t addr) {
    asm volatile("ldmatrix.sync.aligned.m8n8.x4.shared.b16 {%0,%1,%2,%3}, [%4];\n"
        : "=r"(r[0]), "=r"(r[1]), "=r"(r[2]), "=r"(r[3]) : "r"(addr));
}
__device__ __forceinline__ void ldsm_x2(uint32_t* r, uint32_t addr) {
    asm volatile("ldmatrix.sync.aligned.m8n8.x2.shared.b16 {%0,%1}, [%2];\n"
        : "=r"(r[0]), "=r"(r[1]) : "r"(addr));
}
__device__ __forceinline__ void mma_bf16(float* d, const uint32_t* a, const uint32_t* b) {
    asm volatile("mma.sync.aligned.m16n8k16.row.col.f32.bf16.bf16.f32 "
        "{%0,%1,%2,%3}, {%4,%5,%6,%7}, {%8,%9}, {%0,%1,%2,%3};\n"
        : "+f"(d[0]), "+f"(d[1]), "+f"(d[2]), "+f"(d[3])
        : "r"(a[0]), "r"(a[1]), "r"(a[2]), "r"(a[3]), "r"(b[0]), "r"(b[1]));
}
#define CPA(dst, src) \
    asm volatile("cp.async.cg.shared.global [%0], [%1], 16;\n" :: "r"(dst), "l"(src))
#define CP_COMMIT asm volatile("cp.async.commit_group;\n" ::)
#define CP_WAIT1  asm volatile("cp.async.wait_group 1;\n" ::)
#define CP_WAIT0  asm volatile("cp.async.wait_group 0;\n" ::)

// ---------------------------------------------------------------------------
// Shortlist kernel: bf16 tensor-core GEMM (score = 2*xc - c2) + per-thread
// top-8 -> 32 candidate ids per query written to g_cand.
// Tiles: As [2][64][40] bf16 (10240 B), Bs [2][128][40] bf16 (20480 B),
// Stg [64*128] f32 (32768 B) UNIONED with the tiles (tiles dead at staging).
__global__ __launch_bounds__(NT, 2) void shortlist_kernel() {
    __shared__ __align__(128) unsigned char sraw[32768];
    __nv_bfloat16* Asb = (__nv_bfloat16*)sraw;             // offset 0
    __nv_bfloat16* Bsb = (__nv_bfloat16*)(sraw + 10240);
    float*         Stg = (float*)sraw;

    const int tid  = threadIdx.x;
    const int lane = tid & 31;
    const int wid  = tid >> 5;
    const int wm   = (wid >> 2) * 32;      // warp m-origin (0 or 32)
    const int wn   = (wid & 3) * 32;       // warp n-origin (0,32,64,96)
    const int gid  = lane >> 2;
    const int tig  = lane & 3;
    const int mBase = blockIdx.x * BM;

    const uint32_t sA = (uint32_t)__cvta_generic_to_shared(Asb);
    const uint32_t sB = (uint32_t)__cvta_generic_to_shared(Bsb);

    // cp.async source/dest decomposition
    const int a_row = tid >> 2, a_seg = tid & 3;            // 64 rows x 4 segs
    const int b_row = tid >> 1, b_seg = (tid & 1) * 2;      // 128 rows x 4 segs (2/thr)
    const __nv_bfloat16* aSrc = g_Xh + (size_t)(mBase + a_row) * DD + a_seg * 8;
    const uint32_t aDst  = sA + (uint32_t)(a_row * 40 + a_seg * 8) * 2;
    const uint32_t bDst0 = sB + (uint32_t)(b_row * 40 + b_seg * 8) * 2;

    // ldmatrix address bases (row offsets within buffer added per use)
    const int aLdRow = (lane & 15);
    const int aLdCol = 8 * (lane >> 4);
    const int bLdRow = (lane & 7);
    const int bLdCol = 8 * ((lane >> 3) & 1);

    const float NEG_INF = __int_as_float(0xff800000);
    float v0 = NEG_INF, v1 = NEG_INF, v2 = NEG_INF, v3 = NEG_INF;
    float v4 = NEG_INF, v5 = NEG_INF, v6 = NEG_INF, v7 = NEG_INF;
    int j0 = 0x7FFFFFFF, j1 = 0x7FFFFFFF, j2 = 0x7FFFFFFF, j3 = 0x7FFFFFFF;
    int j4 = 0x7FFFFFFF, j5 = 0x7FFFFFFF, j6 = 0x7FFFFFFF, j7 = 0x7FFFFFFF;

    const int q_scan = tid >> 2;           // query this thread scans (0..63)
    const int l4     = tid & 3;            // 32-col slice of the 128-col chunk
    const int rot    = (q_scan + l4 * 8) & 31;

#define PF(KT, BUF)                                                          \
    do {                                                                     \
        CPA(aDst + (BUF) * 5120u, (const void*)(aSrc + (KT) * BK));          \
        CPA(bDst0 + (BUF) * 10240u, (const void*)(bSrc + (KT) * BK));        \
        CPA(bDst0 + (BUF) * 10240u + 16u, (const void*)(bSrc + (KT) * BK + 8)); \
    } while (0)

#pragma unroll 1
    for (int chunk = 0; chunk < NC / BN; ++chunk) {
        const int nBase = chunk * BN;
        const __nv_bfloat16* bSrc = g_Ch + (size_t)(nBase + b_row) * DD + b_seg * 8;

        float ac[2][4][4];
#pragma unroll
        for (int ma = 0; ma < 2; ++ma)
#pragma unroll
            for (int nb = 0; nb < 4; ++nb)
#pragma unroll
                for (int r = 0; r < 4; ++r) ac[ma][nb][r] = 0.f;

        PF(0, 0); CP_COMMIT;

#pragma unroll 1
        for (int kt = 0; kt < DD / BK; ++kt) {
            const int cur = kt & 1;
            if (kt < DD / BK - 1) { PF(kt + 1, cur ^ 1); CP_COMMIT; CP_WAIT1; }
            else                  { CP_WAIT0; }
            __syncthreads();

#pragma unroll
            for (int ks = 0; ks < 2; ++ks) {
                const int k0 = ks * 16;
                uint32_t af[2][4], bf[4][2];
#pragma unroll
                for (int ma = 0; ma < 2; ++ma)
                    ldsm_x4(af[ma], sA + (uint32_t)(((cur * 64) + wm + ma * 16 + aLdRow) * 40
                                                    + k0 + aLdCol) * 2);
#pragma unroll
                for (int nb = 0; nb < 4; ++nb)
                    ldsm_x2(bf[nb], sB + (uint32_t)(((cur * 128) + wn + nb * 8 + bLdRow) * 40
                                                    + k0 + bLdCol) * 2);
#pragma unroll
                for (int ma = 0; ma < 2; ++ma)
#pragma unroll
                    for (int nb = 0; nb < 4; ++nb)
                        mma_bf16(ac[ma][nb], af[ma], bf[nb]);
            }
            __syncthreads();
        }

        // Stage scores psi = 2*dot - c2 into Stg (tiles are dead now).
        {
            float cc[4][2];
#pragma unroll
            for (int nb = 0; nb < 4; ++nb) {
                cc[nb][0] = g_c2[nBase + wn + nb * 8 + 2 * tig];
                cc[nb][1] = g_c2[nBase + wn + nb * 8 + 2 * tig + 1];
            }
#pragma unroll
            for (int ma = 0; ma < 2; ++ma) {
                const int m0 = wm + ma * 16 + gid;
#pragma unroll
                for (int nb = 0; nb < 4; ++nb) {
                    const int n0 = wn + nb * 8 + 2 * tig;
                    Stg[m0 * BN + n0]           = fmaf(2.f, ac[ma][nb][0], -cc[nb][0]);
                    Stg[m0 * BN + n0 + 1]       = fmaf(2.f, ac[ma][nb][1], -cc[nb][1]);
                    Stg[(m0 + 8) * BN + n0]     = fmaf(2.f, ac[ma][nb][2], -cc[nb][0]);
                    Stg[(m0 + 8) * BN + n0 + 1] = fmaf(2.f, ac[ma][nb][3], -cc[nb][1]);
                }
            }
        }
        __syncthreads();

        // Top-8 scan: 4 threads per query, 32 cols each (rotated).
#pragma unroll 1
        for (int j = 0; j < 32; ++j) {
            int jj  = (j + rot) & 31;
            int col = l4 * 32 + jj;
            float s = Stg[q_scan * BN + col];
            int   n = nBase + col;
            TRYINS(s, n)
        }
        __syncthreads();   // protect Stg (aliases next chunk's tiles)
    }
#undef PF

    // Write 32 candidate ids per query (4 threads x 8 each), straight to global.
    int* dst = &g_cand[(size_t)(mBase + q_scan) * NCAND + l4 * 8];
    dst[0] = j0; dst[1] = j1; dst[2] = j2; dst[3] = j3;
    dst[4] = j4; dst[5] = j5; dst[6] = j6; dst[7] = j7;
}

// ---------------------------------------------------------------------------
// Exact rescore of 32 candidates per query (fp32, reference formula),
// exact top-8 pick (value desc, index asc), gather + mean, id output.
// One warp per query; 8 queries per block.
__global__ __launch_bounds__(256) void rescore_kernel(const float* __restrict__ X,
                                                      const float* __restrict__ C,
                                                      float* __restrict__ out,
                                                      float* __restrict__ out_ids)
{
    __shared__ float sv[8][NCAND];
    __shared__ int   si[8][NCAND];
    __shared__ int   sel[8][KSEL];

    const int tid  = threadIdx.x;
    const int wid  = tid >> 5;
    const int lane = tid & 31;
    const int q    = blockIdx.x * 8 + wid;

    const float4* X4 = (const float4*)(X + (size_t)q * DD);
    float4 xr[8];
#pragma unroll
    for (int i = 0; i < 8; ++i) xr[i] = X4[i * 32 + lane];
    const float x2 = g_x2[q];

#pragma unroll 1
    for (int c = 0; c < NCAND; ++c) {
        const int id = g_cand[(size_t)q * NCAND + c];
        const float4* C4 = (const float4*)(C + (size_t)id * DD);
        float s = 0.f;
#pragma unroll
        for (int i = 0; i < 8; ++i) {
            float4 cv = C4[i * 32 + lane];
            s += xr[i].x * cv.x + xr[i].y * cv.y + xr[i].z * cv.z + xr[i].w * cv.w;
        }
#pragma unroll
        for (int o = 16; o > 0; o >>= 1) s += __shfl_xor_sync(0xffffffffu, s, o);
        if (lane == 0) {
            sv[wid][c] = -(fmaf(-2.f, s, x2) + g_c2[id]);   // reference formula order
            si[wid][c] = id;
        }
    }
    __syncwarp();

    if (lane == 0) {
        const float NEG_INF = __int_as_float(0xff800000);
        float v0 = NEG_INF, v1 = NEG_INF, v2 = NEG_INF, v3 = NEG_INF;
        float v4 = NEG_INF, v5 = NEG_INF, v6 = NEG_INF, v7 = NEG_INF;
        int j0 = 0x7FFFFFFF, j1 = 0x7FFFFFFF, j2 = 0x7FFFFFFF, j3 = 0x7FFFFFFF;
        int j4 = 0x7FFFFFFF, j5 = 0x7FFFFFFF, j6 = 0x7FFFFFFF, j7 = 0x7FFFFFFF;
#pragma unroll 1
        for (int c = 0; c < NCAND; ++c) {
            float s = sv[wid][c];
            int   n = si[wid][c];
            TRYINS(s, n)
        }
        sel[wid][0] = j0; sel[wid][1] = j1; sel[wid][2] = j2; sel[wid][3] = j3;
        sel[wid][4] = j4; sel[wid][5] = j5; sel[wid][6] = j6; sel[wid][7] = j7;
        if (out_ids) {
            float* o = out_ids + (size_t)q * KSEL;
            o[0] = (float)j0; o[1] = (float)j1; o[2] = (float)j2; o[3] = (float)j3;
            o[4] = (float)j4; o[5] = (float)j5; o[6] = (float)j6; o[7] = (float)j7;
        }
    }
    __syncwarp();

    // Gather + mean
    const float4* P0 = (const float4*)(C + (size_t)sel[wid][0] * DD);
    const float4* P1 = (const float4*)(C + (size_t)sel[wid][1] * DD);
    const float4* P2 = (const float4*)(C + (size_t)sel[wid][2] * DD);
    const float4* P3 = (const float4*)(C + (size_t)sel[wid][3] * DD);
    const float4* P4 = (const float4*)(C + (size_t)sel[wid][4] * DD);
    const float4* P5 = (const float4*)(C + (size_t)sel[wid][5] * DD);
    const float4* P6 = (const float4*)(C + (size_t)sel[wid][6] * DD);
    const float4* P7 = (const float4*)(C + (size_t)sel[wid][7] * DD);
    float4* O4 = (float4*)(out + (size_t)q * DD);
#pragma unroll
    for (int i = 0; i < 8; ++i) {
        const int f = i * 32 + lane;
        float4 a0 = P0[f], a1 = P1[f], a2 = P2[f], a3 = P3[f];
        float4 a4 = P4[f], a5 = P5[f], a6 = P6[f], a7 = P7[f];
        float4 r;
        r.x = (a0.x + a1.x + a2.x + a3.x + a4.x + a5.x + a6.x + a7.x) * 0.125f;
        r.y = (a0.y + a1.y + a2.y + a3.y + a4.y + a5.y + a6.y + a7.y) * 0.125f;
        r.z = (a0.z + a1.z + a2.z + a3.z + a4.z + a5.z + a6.z + a7.z) * 0.125f;
        r.w = (a0.w + a1.w + a2.w + a3.w + a4.w + a5.w + a6.w + a7.w) * 0.125f;
        O4[f] = r;
    }
}

// ---------------------------------------------------------------------------
extern "C" void kernel_launch(void* const* d_in, const int* in_sizes, int n_in,
                              void* d_out, int out_size)
{
    const float* X = (const float*)d_in[0];   // inputs  [4,2048,1024] f32
    const float* C = (const float*)d_in[1];   // codebook [16384,1024] f32
    // d_in[2] = kcodes (scalar, fixed at 8)

    float* out     = (float*)d_out;
    float* out_ids = nullptr;
    if (out_size >= MQ * DD + MQ * KSEL)
        out_ids = out + (size_t)MQ * DD;      // ids appended after outputs

    cnorm_kernel<<<NC / 8, 256>>>(C);
    xnorm_kernel<<<MQ / 8, 256>>>(X);
    cvtX_kernel<<<MQ * DD / 1024, 256>>>(X);
    cvtC_kernel<<<NC * DD / 1024, 256>>>(C);
    shortlist_kernel<<<MQ / BM, NT>>>();
    rescore_kernel<<<MQ / 8, 256>>>(X, C, out, out_ids);
}

// round 9
// speedup vs baseline: 7.2069x; 1.2469x over previous
#include <cuda_runtime.h>
#include <cuda_bf16.h>
#include <stdint.h>

// Problem dims
#define MQ    8192
#define DD    1024
#define NC    16384
#define KSEL  8
#define NCAND 32

// Shortlist GEMM tiling: 128 queries x 128-code chunks, warp tile 32x64
#define BM 128
#define BN 128
#define BK 32
#define NT 256
#define NSPLIT 2
#define CODES_PER_CTA (NC / NSPLIT)      // 8192
#define NCHUNK (CODES_PER_CTA / BN)      // 64

#define STAGE_BYTES 20480u               // A(128x40 bf16) + B(128x40 bf16)
#define SMEM_BYTES  65536                // union(2 stages=40960, Stg 128*128*4)

// ---------------------------------------------------------------------------
__device__ float            g_c2[NC];
__device__ float            g_x2[MQ];
__device__ __nv_bfloat16    g_Xh[(size_t)MQ * DD];
__device__ __nv_bfloat16    g_Ch[(size_t)NC * DD];
__device__ int              g_cand[(size_t)MQ * NCAND];

// ---------------------------------------------------------------------------
__global__ void cnorm_kernel(const float* __restrict__ src) {
    int row = blockIdx.x * 8 + (threadIdx.x >> 5);
    if (row >= NC) return;
    int lane = threadIdx.x & 31;
    const float4* r4 = (const float4*)(src + (size_t)row * DD);
    float s = 0.f;
#pragma unroll
    for (int i = 0; i < 8; ++i) {
        float4 v = r4[i * 32 + lane];
        s += v.x * v.x + v.y * v.y + v.z * v.z + v.w * v.w;
    }
#pragma unroll
    for (int o = 16; o > 0; o >>= 1) s += __shfl_xor_sync(0xffffffffu, s, o);
    if (lane == 0) g_c2[row] = s;
}

__global__ void xnorm_kernel(const float* __restrict__ src) {
    int row = blockIdx.x * 8 + (threadIdx.x >> 5);
    if (row >= MQ) return;
    int lane = threadIdx.x & 31;
    const float4* r4 = (const float4*)(src + (size_t)row * DD);
    float s = 0.f;
#pragma unroll
    for (int i = 0; i < 8; ++i) {
        float4 v = r4[i * 32 + lane];
        s += v.x * v.x + v.y * v.y + v.z * v.z + v.w * v.w;
    }
#pragma unroll
    for (int o = 16; o > 0; o >>= 1) s += __shfl_xor_sync(0xffffffffu, s, o);
    if (lane == 0) g_x2[row] = s;
}

__global__ void cvtX_kernel(const float* __restrict__ src) {
    size_t gi = (size_t)blockIdx.x * 256 + threadIdx.x;
    float4 v = ((const float4*)src)[gi];
    __nv_bfloat162* dst = (__nv_bfloat162*)&g_Xh[gi * 4];
    dst[0] = __floats2bfloat162_rn(v.x, v.y);
    dst[1] = __floats2bfloat162_rn(v.z, v.w);
}
__global__ void cvtC_kernel(const float* __restrict__ src) {
    size_t gi = (size_t)blockIdx.x * 256 + threadIdx.x;
    float4 v = ((const float4*)src)[gi];
    __nv_bfloat162* dst = (__nv_bfloat162*)&g_Ch[gi * 4];
    dst[0] = __floats2bfloat162_rn(v.x, v.y);
    dst[1] = __floats2bfloat162_rn(v.z, v.w);
}

// ---------------------------------------------------------------------------
// Scalar top-8 (value desc; ties -> smaller index first, matching JAX top_k)
#define BUBBLE(va, ia, vb, ib)                                    \
    if (va > vb || (va == vb && ia < ib)) {                       \
        float _tv = va; va = vb; vb = _tv;                        \
        int   _ti = ia; ia = ib; ib = _ti;                        \
    }
#define TRYINS(s, n)                                              \
    if ((s) > v7 || ((s) == v7 && (n) < j7)) {                    \
        v7 = (s); j7 = (n);                                       \
        BUBBLE(v7, j7, v6, j6)                                    \
        BUBBLE(v6, j6, v5, j5)                                    \
        BUBBLE(v5, j5, v4, j4)                                    \
        BUBBLE(v4, j4, v3, j3)                                    \
        BUBBLE(v3, j3, v2, j2)                                    \
        BUBBLE(v2, j2, v1, j1)                                    \
        BUBBLE(v1, j1, v0, j0)                                    \
    }

// ---------------------------------------------------------------------------
// PTX wrappers
__device__ __forceinline__ void ldsm_x4(uint32_t* r, uint32_t addr) {
    asm volatile("ldmatrix.sync.aligned.m8n8.x4.shared.b16 {%0,%1,%2,%3}, [%4];\n"
        : "=r"(r[0]), "=r"(r[1]), "=r"(r[2]), "=r"(r[3]) : "r"(addr));
}
__device__ __forceinline__ void mma_bf16(float* d, const uint32_t* a, const uint32_t* b) {
    asm volatile("mma.sync.aligned.m16n8k16.row.col.f32.bf16.bf16.f32 "
        "{%0,%1,%2,%3}, {%4,%5,%6,%7}, {%8,%9}, {%0,%1,%2,%3};\n"
        : "+f"(d[0]), "+f"(d[1]), "+f"(d[2]), "+f"(d[3])
        : "r"(a[0]), "r"(a[1]), "r"(a[2]), "r"(a[3]), "r"(b[0]), "r"(b[1]));
}
#define CPA(dst, src) \
    asm volatile("cp.async.cg.shared.global [%0], [%1], 16;\n" :: "r"(dst), "l"(src))
#define CP_COMMIT asm volatile("cp.async.commit_group;\n" ::)
#define CP_WAIT1  asm volatile("cp.async.wait_group 1;\n" ::)
#define CP_WAIT0  asm volatile("cp.async.wait_group 0;\n" ::)

// ---------------------------------------------------------------------------
// Shortlist kernel: bf16 mma.sync GEMM (score = 2*xc - c2) + per-thread top-8.
// Grid (MQ/BM, NSPLIT). Each CTA: 128 queries x 8192 codes in 64 chunks.
__global__ void __launch_bounds__(NT, 1) shortlist_kernel() {
    extern __shared__ __align__(128) unsigned char sraw[];
    float* Stg = (float*)sraw;                      // aliases both stages

    const int tid  = threadIdx.x;
    const int lane = tid & 31;
    const int wid  = tid >> 5;
    const int wm   = (wid >> 1) * 32;               // warp m-origin: 0,32,64,96
    const int wn   = (wid & 1) * 64;                // warp n-origin: 0,64
    const int gid  = lane >> 2;
    const int tig  = lane & 3;
    const int mBase = blockIdx.x * BM;
    const int cBase = blockIdx.y * CODES_PER_CTA;

    const uint32_t sBase = (uint32_t)__cvta_generic_to_shared(sraw);

    // cp.async decomposition: A and B each 128 rows x 4 16B-segs; 2 segs/thread.
    const int ld_row = tid >> 1;
    const int ld_s0  = (tid & 1) * 2;
    const __nv_bfloat16* aSrc = g_Xh + (size_t)(mBase + ld_row) * DD + ld_s0 * 8;
    const uint32_t aDst = sBase + (uint32_t)(ld_row * 40 + ld_s0 * 8) * 2;
    const uint32_t bDst = aDst + 10240u;

    // ldmatrix lane->address maps
    const int aLdRow = lane & 15;
    const int aLdCol = 8 * (lane >> 4);
    const int bLdRow = (lane & 7) + ((lane >> 4) << 3);
    const int bLdCol = ((lane >> 3) & 1) * 8;

    const float NEG_INF = __int_as_float(0xff800000);
    float v0 = NEG_INF, v1 = NEG_INF, v2 = NEG_INF, v3 = NEG_INF;
    float v4 = NEG_INF, v5 = NEG_INF, v6 = NEG_INF, v7 = NEG_INF;
    int j0 = 0x7FFFFFFF, j1 = 0x7FFFFFFF, j2 = 0x7FFFFFFF, j3 = 0x7FFFFFFF;
    int j4 = 0x7FFFFFFF, j5 = 0x7FFFFFFF, j6 = 0x7FFFFFFF, j7 = 0x7FFFFFFF;

    const int q_scan = tid >> 1;                    // query row (0..127)
    const int l2     = tid & 1;                     // 64-col slice

#define PF(KT, BUF)                                                           \
    do {                                                                      \
        uint32_t so = (BUF) * STAGE_BYTES;                                    \
        CPA(aDst + so,       (const void*)(aSrc + (KT) * BK));                \
        CPA(aDst + so + 16u, (const void*)(aSrc + (KT) * BK + 8));            \
        CPA(bDst + so,       (const void*)(bSrc + (KT) * BK));                \
        CPA(bDst + so + 16u, (const void*)(bSrc + (KT) * BK + 8));            \
    } while (0)

#pragma unroll 1
    for (int chunk = 0; chunk < NCHUNK; ++chunk) {
        const int nBase = chunk * BN;
        const __nv_bfloat16* bSrc =
            g_Ch + (size_t)(cBase + nBase + ld_row) * DD + ld_s0 * 8;

        float ac[2][8][4];
#pragma unroll
        for (int ma = 0; ma < 2; ++ma)
#pragma unroll
            for (int nb = 0; nb < 8; ++nb)
#pragma unroll
                for (int r = 0; r < 4; ++r) ac[ma][nb][r] = 0.f;

        PF(0, 0); CP_COMMIT;

#pragma unroll 1
        for (int kt = 0; kt < DD / BK; ++kt) {
            const int cur = kt & 1;
            if (kt < DD / BK - 1) { PF(kt + 1, cur ^ 1); CP_COMMIT; CP_WAIT1; }
            else                  { CP_WAIT0; }
            __syncthreads();

            const uint32_t sA = sBase + (uint32_t)cur * STAGE_BYTES;
            const uint32_t sB = sA + 10240u;
#pragma unroll
            for (int ks = 0; ks < 2; ++ks) {
                const int k0 = ks * 16;
                uint32_t af[2][4], bf[8][2];
#pragma unroll
                for (int ma = 0; ma < 2; ++ma)
                    ldsm_x4(af[ma],
                            sA + (uint32_t)((wm + ma * 16 + aLdRow) * 40 + k0 + aLdCol) * 2);
#pragma unroll
                for (int nq = 0; nq < 4; ++nq) {
                    uint32_t t[4];
                    ldsm_x4(t, sB + (uint32_t)((wn + nq * 16 + bLdRow) * 40 + k0 + bLdCol) * 2);
                    bf[nq * 2][0] = t[0]; bf[nq * 2][1] = t[1];
                    bf[nq * 2 + 1][0] = t[2]; bf[nq * 2 + 1][1] = t[3];
                }
#pragma unroll
                for (int ma = 0; ma < 2; ++ma)
#pragma unroll
                    for (int nb = 0; nb < 8; ++nb)
                        mma_bf16(ac[ma][nb], af[ma], bf[nb]);
            }
            __syncthreads();
        }

        // Stage scores psi = 2*dot - c2 into Stg (tiles dead now).
        {
#pragma unroll
            for (int ma = 0; ma < 2; ++ma) {
                const int m0 = wm + ma * 16 + gid;
#pragma unroll
                for (int nb = 0; nb < 8; ++nb) {
                    const int n0 = wn + nb * 8 + 2 * tig;
                    const float cc0 = g_c2[cBase + nBase + n0];
                    const float cc1 = g_c2[cBase + nBase + n0 + 1];
                    Stg[m0 * BN + n0]           = fmaf(2.f, ac[ma][nb][0], -cc0);
                    Stg[m0 * BN + n0 + 1]       = fmaf(2.f, ac[ma][nb][1], -cc1);
                    Stg[(m0 + 8) * BN + n0]     = fmaf(2.f, ac[ma][nb][2], -cc0);
                    Stg[(m0 + 8) * BN + n0 + 1] = fmaf(2.f, ac[ma][nb][3], -cc1);
                }
            }
        }
        __syncthreads();

        // Top-8 scan: 2 threads per query, 64 cols each (conflict-free rotation).
#pragma unroll 1
        for (int j = 0; j < 64; ++j) {
            int jj  = (j + lane) & 63;
            int col = l2 * 64 + jj;
            float s = Stg[q_scan * BN + col];
            int   n = cBase + nBase + col;
            TRYINS(s, n)
        }
        __syncthreads();   // protect Stg (aliases next chunk's tiles)
    }
#undef PF

    // Write 16 candidate ids per (query, split): 2 threads x 8 each.
    int* dst = &g_cand[(size_t)(mBase + q_scan) * NCAND + blockIdx.y * 16 + l2 * 8];
    dst[0] = j0; dst[1] = j1; dst[2] = j2; dst[3] = j3;
    dst[4] = j4; dst[5] = j5; dst[6] = j6; dst[7] = j7;
}

// ---------------------------------------------------------------------------
// Exact fp32 rescore of 32 candidates/query + top-8 + gather/mean.
__global__ void __launch_bounds__(256) rescore_kernel(const float* __restrict__ X,
                                                      const float* __restrict__ C,
                                                      float* __restrict__ out,
                                                      float* __restrict__ out_ids)
{
    __shared__ float sv[8][NCAND];
    __shared__ int   si[8][NCAND];
    __shared__ int   sel[8][KSEL];

    const int tid  = threadIdx.x;
    const int wid  = tid >> 5;
    const int lane = tid & 31;
    const int q    = blockIdx.x * 8 + wid;

    const float4* X4 = (const float4*)(X + (size_t)q * DD);
    float4 xr[8];
#pragma unroll
    for (int i = 0; i < 8; ++i) xr[i] = X4[i * 32 + lane];
    const float x2 = g_x2[q];

#pragma unroll 1
    for (int c = 0; c < NCAND; ++c) {
        const int id = g_cand[(size_t)q * NCAND + c];
        const float4* C4 = (const float4*)(C + (size_t)id * DD);
        float s = 0.f;
#pragma unroll
        for (int i = 0; i < 8; ++i) {
            float4 cv = C4[i * 32 + lane];
            s += xr[i].x * cv.x + xr[i].y * cv.y + xr[i].z * cv.z + xr[i].w * cv.w;
        }
#pragma unroll
        for (int o = 16; o > 0; o >>= 1) s += __shfl_xor_sync(0xffffffffu, s, o);
        if (lane == 0) {
            sv[wid][c] = -(fmaf(-2.f, s, x2) + g_c2[id]);   // reference formula order
            si[wid][c] = id;
        }
    }
    __syncwarp();

    if (lane == 0) {
        const float NEG_INF = __int_as_float(0xff800000);
        float v0 = NEG_INF, v1 = NEG_INF, v2 = NEG_INF, v3 = NEG_INF;
        float v4 = NEG_INF, v5 = NEG_INF, v6 = NEG_INF, v7 = NEG_INF;
        int j0 = 0x7FFFFFFF, j1 = 0x7FFFFFFF, j2 = 0x7FFFFFFF, j3 = 0x7FFFFFFF;
        int j4 = 0x7FFFFFFF, j5 = 0x7FFFFFFF, j6 = 0x7FFFFFFF, j7 = 0x7FFFFFFF;
#pragma unroll 1
        for (int c = 0; c < NCAND; ++c) {
            float s = sv[wid][c];
            int   n = si[wid][c];
            TRYINS(s, n)
        }
        sel[wid][0] = j0; sel[wid][1] = j1; sel[wid][2] = j2; sel[wid][3] = j3;
        sel[wid][4] = j4; sel[wid][5] = j5; sel[wid][6] = j6; sel[wid][7] = j7;
        if (out_ids) {
            float* o = out_ids + (size_t)q * KSEL;
            o[0] = (float)j0; o[1] = (float)j1; o[2] = (float)j2; o[3] = (float)j3;
            o[4] = (float)j4; o[5] = (float)j5; o[6] = (float)j6; o[7] = (float)j7;
        }
    }
    __syncwarp();

    const float4* P0 = (const float4*)(C + (size_t)sel[wid][0] * DD);
    const float4* P1 = (const float4*)(C + (size_t)sel[wid][1] * DD);
    const float4* P2 = (const float4*)(C + (size_t)sel[wid][2] * DD);
    const float4* P3 = (const float4*)(C + (size_t)sel[wid][3] * DD);
    const float4* P4 = (const float4*)(C + (size_t)sel[wid][4] * DD);
    const float4* P5 = (const float4*)(C + (size_t)sel[wid][5] * DD);
    const float4* P6 = (const float4*)(C + (size_t)sel[wid][6] * DD);
    const float4* P7 = (const float4*)(C + (size_t)sel[wid][7] * DD);
    float4* O4 = (float4*)(out + (size_t)q * DD);
#pragma unroll
    for (int i = 0; i < 8; ++i) {
        const int f = i * 32 + lane;
        float4 a0 = P0[f], a1 = P1[f], a2 = P2[f], a3 = P3[f];
        float4 a4 = P4[f], a5 = P5[f], a6 = P6[f], a7 = P7[f];
        float4 rr;
        rr.x = (a0.x + a1.x + a2.x + a3.x + a4.x + a5.x + a6.x + a7.x) * 0.125f;
        rr.y = (a0.y + a1.y + a2.y + a3.y + a4.y + a5.y + a6.y + a7.y) * 0.125f;
        rr.z = (a0.z + a1.z + a2.z + a3.z + a4.z + a5.z + a6.z + a7.z) * 0.125f;
        rr.w = (a0.w + a1.w + a2.w + a3.w + a4.w + a5.w + a6.w + a7.w) * 0.125f;
        O4[f] = rr;
    }
}

// ---------------------------------------------------------------------------
extern "C" void kernel_launch(void* const* d_in, const int* in_sizes, int n_in,
                              void* d_out, int out_size)
{
    const float* X = (const float*)d_in[0];   // inputs   [4,2048,1024] f32
    const float* C = (const float*)d_in[1];   // codebook [16384,1024] f32

    float* out     = (float*)d_out;
    float* out_ids = nullptr;
    if (out_size >= MQ * DD + MQ * KSEL)
        out_ids = out + (size_t)MQ * DD;

    cnorm_kernel<<<NC / 8, 256>>>(C);
    xnorm_kernel<<<MQ / 8, 256>>>(X);
    cvtX_kernel<<<MQ * DD / 1024, 256>>>(X);
    cvtC_kernel<<<NC * DD / 1024, 256>>>(C);

    cudaFuncSetAttribute(shortlist_kernel,
                         cudaFuncAttributeMaxDynamicSharedMemorySize, SMEM_BYTES);
    dim3 grid(MQ / BM, NSPLIT);
    shortlist_kernel<<<grid, NT, SMEM_BYTES>>>();

    rescore_kernel<<<MQ / 8, 256>>>(X, C, out, out_ids);
}

// round 11
// speedup vs baseline: 7.3755x; 1.0234x over previous
#include <cuda_runtime.h>
#include <cuda_bf16.h>
#include <stdint.h>

// Problem dims
#define MQ    8192
#define DD    1024
#define NC    16384
#define KSEL  8
#define NCAND 32

// Shortlist GEMM tiling: 128 queries x 128-code chunks, warp tile 32x64
#define BM 128
#define BN 128
#define BK 32
#define NT 256
#define NSPLIT 2
#define CODES_PER_CTA (NC / NSPLIT)      // 8192
#define NCHUNK (CODES_PER_CTA / BN)      // 64
#define NKT    (DD / BK)                 // 32

#define STAGE_BYTES 20480u               // A(128x40 bf16) + B(128x40 bf16)
#define NSTAGE 3
#define STG_OFF (NSTAGE * STAGE_BYTES)   // 61440
#define SMEM_BYTES (STG_OFF + BM * BN * 4)  // 61440 + 65536 = 126976

// ---------------------------------------------------------------------------
__device__ float            g_c2[NC];
__device__ float            g_x2[MQ];
__device__ __nv_bfloat16    g_Xh[(size_t)MQ * DD];
__device__ __nv_bfloat16    g_Ch[(size_t)NC * DD];
__device__ int              g_cand[(size_t)MQ * NCAND];

// ---------------------------------------------------------------------------
// Fused convert(bf16) + squared-norm kernels: one warp per row, single pass.
__global__ void cprep_kernel(const float* __restrict__ src) {
    int row = blockIdx.x * 8 + (threadIdx.x >> 5);
    if (row >= NC) return;
    int lane = threadIdx.x & 31;
    const float4* r4 = (const float4*)(src + (size_t)row * DD);
    uint2* dst = (uint2*)(g_Ch + (size_t)row * DD);
    float s = 0.f;
#pragma unroll
    for (int i = 0; i < 8; ++i) {
        float4 v = r4[i * 32 + lane];
        s += v.x * v.x + v.y * v.y + v.z * v.z + v.w * v.w;
        __nv_bfloat162 lo = __floats2bfloat162_rn(v.x, v.y);
        __nv_bfloat162 hi = __floats2bfloat162_rn(v.z, v.w);
        uint2 u;
        u.x = *(uint32_t*)&lo;
        u.y = *(uint32_t*)&hi;
        dst[i * 32 + lane] = u;
    }
#pragma unroll
    for (int o = 16; o > 0; o >>= 1) s += __shfl_xor_sync(0xffffffffu, s, o);
    if (lane == 0) g_c2[row] = s;
}

__global__ void xprep_kernel(const float* __restrict__ src) {
    int row = blockIdx.x * 8 + (threadIdx.x >> 5);
    if (row >= MQ) return;
    int lane = threadIdx.x & 31;
    const float4* r4 = (const float4*)(src + (size_t)row * DD);
    uint2* dst = (uint2*)(g_Xh + (size_t)row * DD);
    float s = 0.f;
#pragma unroll
    for (int i = 0; i < 8; ++i) {
        float4 v = r4[i * 32 + lane];
        s += v.x * v.x + v.y * v.y + v.z * v.z + v.w * v.w;
        __nv_bfloat162 lo = __floats2bfloat162_rn(v.x, v.y);
        __nv_bfloat162 hi = __floats2bfloat162_rn(v.z, v.w);
        uint2 u;
        u.x = *(uint32_t*)&lo;
        u.y = *(uint32_t*)&hi;
        dst[i * 32 + lane] = u;
    }
#pragma unroll
    for (int o = 16; o > 0; o >>= 1) s += __shfl_xor_sync(0xffffffffu, s, o);
    if (lane == 0) g_x2[row] = s;
}

// ---------------------------------------------------------------------------
// Scalar top-8 (value desc; ties -> smaller index first, matching JAX top_k)
#define BUBBLE(va, ia, vb, ib)                                    \
    if (va > vb || (va == vb && ia < ib)) {                       \
        float _tv = va; va = vb; vb = _tv;                        \
        int   _ti = ia; ia = ib; ib = _ti;                        \
    }
#define TRYINS(s, n)                                              \
    if ((s) > v7 || ((s) == v7 && (n) < j7)) {                    \
        v7 = (s); j7 = (n);                                       \
        BUBBLE(v7, j7, v6, j6)                                    \
        BUBBLE(v6, j6, v5, j5)                                    \
        BUBBLE(v5, j5, v4, j4)                                    \
        BUBBLE(v4, j4, v3, j3)                                    \
        BUBBLE(v3, j3, v2, j2)                                    \
        BUBBLE(v2, j2, v1, j1)                                    \
        BUBBLE(v1, j1, v0, j0)                                    \
    }

// ---------------------------------------------------------------------------
// PTX wrappers
__device__ __forceinline__ void ldsm_x4(uint32_t* r, uint32_t addr) {
    asm volatile("ldmatrix.sync.aligned.m8n8.x4.shared.b16 {%0,%1,%2,%3}, [%4];\n"
        : "=r"(r[0]), "=r"(r[1]), "=r"(r[2]), "=r"(r[3]) : "r"(addr));
}
__device__ __forceinline__ void mma_bf16(float* d, const uint32_t* a, const uint32_t* b) {
    asm volatile("mma.sync.aligned.m16n8k16.row.col.f32.bf16.bf16.f32 "
        "{%0,%1,%2,%3}, {%4,%5,%6,%7}, {%8,%9}, {%0,%1,%2,%3};\n"
        : "+f"(d[0]), "+f"(d[1]), "+f"(d[2]), "+f"(d[3])
        : "r"(a[0]), "r"(a[1]), "r"(a[2]), "r"(a[3]), "r"(b[0]), "r"(b[1]));
}
#define CPA(dst, src) \
    asm volatile("cp.async.cg.shared.global [%0], [%1], 16;\n" :: "r"(dst), "l"(src))
#define CP_COMMIT asm volatile("cp.async.commit_group;\n" ::)
#define CP_WAIT1  asm volatile("cp.async.wait_group 1;\n" ::)
#define CP_WAIT0  asm volatile("cp.async.wait_group 0;\n" ::)

// ---------------------------------------------------------------------------
// Shortlist kernel: bf16 mma.sync GEMM (score = 2*xc - c2) + per-thread top-8.
// 3-stage cp.async pipeline, ONE __syncthreads per K-step; Stg has its own
// smem so the per-chunk scan overlaps the next chunk's first prefetches.
__global__ void __launch_bounds__(NT, 1) shortlist_kernel() {
    extern __shared__ __align__(128) unsigned char sraw[];
    float* Stg = (float*)(sraw + STG_OFF);

    const int tid  = threadIdx.x;
    const int lane = tid & 31;
    const int wid  = tid >> 5;
    const int wm   = (wid >> 1) * 32;               // warp m-origin: 0,32,64,96
    const int wn   = (wid & 1) * 64;                // warp n-origin: 0,64
    const int gid  = lane >> 2;
    const int tig  = lane & 3;
    const int mBase = blockIdx.x * BM;
    const int cBase = blockIdx.y * CODES_PER_CTA;

    const uint32_t sBase = (uint32_t)__cvta_generic_to_shared(sraw);

    // cp.async decomposition: A and B each 128 rows x 4 16B-segs; 2 segs/thread.
    const int ld_row = tid >> 1;
    const int ld_s0  = (tid & 1) * 2;
    const __nv_bfloat16* aSrc = g_Xh + (size_t)(mBase + ld_row) * DD + ld_s0 * 8;
    const uint32_t aDst = sBase + (uint32_t)(ld_row * 40 + ld_s0 * 8) * 2;
    const uint32_t bDst = aDst + 10240u;

    // ldmatrix lane->address maps
    const int aLdRow = lane & 15;
    const int aLdCol = 8 * (lane >> 4);
    const int bLdRow = (lane & 7) + ((lane >> 4) << 3);
    const int bLdCol = ((lane >> 3) & 1) * 8;

    const float NEG_INF = __int_as_float(0xff800000);
    float v0 = NEG_INF, v1 = NEG_INF, v2 = NEG_INF, v3 = NEG_INF;
    float v4 = NEG_INF, v5 = NEG_INF, v6 = NEG_INF, v7 = NEG_INF;
    int j0 = 0x7FFFFFFF, j1 = 0x7FFFFFFF, j2 = 0x7FFFFFFF, j3 = 0x7FFFFFFF;
    int j4 = 0x7FFFFFFF, j5 = 0x7FFFFFFF, j6 = 0x7FFFFFFF, j7 = 0x7FFFFFFF;

    const int q_scan = tid >> 1;                    // query row (0..127)
    const int l2     = tid & 1;                     // 64-col slice

    // PF: prefetch K-slab KT of the current chunk's A/B into stage buffer BUF.
#define PF(SRC, KT, BUF)                                                      \
    do {                                                                      \
        uint32_t so = (uint32_t)(BUF) * STAGE_BYTES;                          \
        CPA(aDst + so,       (const void*)(aSrc + (KT) * BK));                \
        CPA(aDst + so + 16u, (const void*)(aSrc + (KT) * BK + 8));            \
        CPA(bDst + so,       (const void*)((SRC) + (KT) * BK));               \
        CPA(bDst + so + 16u, (const void*)((SRC) + (KT) * BK + 8));           \
        CP_COMMIT;                                                            \
    } while (0)

    const __nv_bfloat16* bSrc =
        g_Ch + (size_t)(cBase + ld_row) * DD + ld_s0 * 8;

    // chunk-0 prologue: stages 0,1 -> bufs 0,1
    PF(bSrc, 0, 0);
    PF(bSrc, 1, 1);

#pragma unroll 1
    for (int chunk = 0; chunk < NCHUNK; ++chunk) {
        const int nBase = chunk * BN;

        float ac[2][8][4];
#pragma unroll
        for (int ma = 0; ma < 2; ++ma)
#pragma unroll
            for (int nb = 0; nb < 8; ++nb)
#pragma unroll
                for (int r = 0; r < 4; ++r) ac[ma][nb][r] = 0.f;

#pragma unroll 1
        for (int kt = 0; kt < NKT; ++kt) {
            if (kt < NKT - 1) { CP_WAIT1; } else { CP_WAIT0; }
            __syncthreads();
            if (kt + 2 < NKT) PF(bSrc, kt + 2, (kt + 2) % NSTAGE);

            const uint32_t sA = sBase + (uint32_t)(kt % NSTAGE) * STAGE_BYTES;
            const uint32_t sB = sA + 10240u;
#pragma unroll
            for (int ks = 0; ks < 2; ++ks) {
                const int k0 = ks * 16;
                uint32_t af[2][4], bf[8][2];
#pragma unroll
                for (int ma = 0; ma < 2; ++ma)
                    ldsm_x4(af[ma],
                            sA + (uint32_t)((wm + ma * 16 + aLdRow) * 40 + k0 + aLdCol) * 2);
#pragma unroll
                for (int nq = 0; nq < 4; ++nq) {
                    uint32_t t[4];
                    ldsm_x4(t, sB + (uint32_t)((wn + nq * 16 + bLdRow) * 40 + k0 + bLdCol) * 2);
                    bf[nq * 2][0] = t[0]; bf[nq * 2][1] = t[1];
                    bf[nq * 2 + 1][0] = t[2]; bf[nq * 2 + 1][1] = t[3];
                }
#pragma unroll
                for (int ma = 0; ma < 2; ++ma)
#pragma unroll
                    for (int nb = 0; nb < 8; ++nb)
                        mma_bf16(ac[ma][nb], af[ma], bf[nb]);
            }
        }
        // NOTE: after the kt=NKT-1 top-sync, all warps have consumed stages
        // NKT-3 (buf0-congruent) and earlier -> buf (0 mod 3) is free for the
        // next chunk's stage 0 right now; buf for stage 1 frees after the
        // staging sync below.

        const __nv_bfloat16* bNext =
            g_Ch + (size_t)(cBase + nBase + BN + ld_row) * DD + ld_s0 * 8;
        if (chunk + 1 < NCHUNK) PF(bNext, 0, 0);   // stage0 -> buf0 (safe)

        // Stage scores psi = 2*dot - c2 into Stg (separate memory).
#pragma unroll
        for (int ma = 0; ma < 2; ++ma) {
            const int m0 = wm + ma * 16 + gid;
#pragma unroll
            for (int nb = 0; nb < 8; ++nb) {
                const int n0 = wn + nb * 8 + 2 * tig;
                const float cc0 = g_c2[cBase + nBase + n0];
                const float cc1 = g_c2[cBase + nBase + n0 + 1];
                Stg[m0 * BN + n0]           = fmaf(2.f, ac[ma][nb][0], -cc0);
                Stg[m0 * BN + n0 + 1]       = fmaf(2.f, ac[ma][nb][1], -cc1);
                Stg[(m0 + 8) * BN + n0]     = fmaf(2.f, ac[ma][nb][2], -cc0);
                Stg[(m0 + 8) * BN + n0 + 1] = fmaf(2.f, ac[ma][nb][3], -cc1);
            }
        }
        __syncthreads();                            // staging visible; buf1 free
        if (chunk + 1 < NCHUNK) PF(bNext, 1, 1);    // stage1 -> buf1

        // Top-8 scan overlaps the in-flight prefetches.
#pragma unroll 1
        for (int j = 0; j < 64; ++j) {
            int jj  = (j + lane) & 63;
            int col = l2 * 64 + jj;
            float s = Stg[q_scan * BN + col];
            int   n = cBase + nBase + col;
            TRYINS(s, n)
        }
        __syncthreads();                            // Stg reusable next chunk
        bSrc = bNext;
    }
#undef PF

    // Write 16 candidate ids per (query, split): 2 threads x 8 each.
    int* dst = &g_cand[(size_t)(mBase + q_scan) * NCAND + blockIdx.y * 16 + l2 * 8];
    dst[0] = j0; dst[1] = j1; dst[2] = j2; dst[3] = j3;
    dst[4] = j4; dst[5] = j5; dst[6] = j6; dst[7] = j7;
}

// ---------------------------------------------------------------------------
// Exact fp32 rescore of 32 candidates/query + top-8 + gather/mean.
__global__ void __launch_bounds__(256) rescore_kernel(const float* __restrict__ X,
                                                      const float* __restrict__ C,
                                                      float* __restrict__ out,
                                                      float* __restrict__ out_ids)
{
    __shared__ float sv[8][NCAND];
    __shared__ int   si[8][NCAND];
    __shared__ int   sel[8][KSEL];

    const int tid  = threadIdx.x;
    const int wid  = tid >> 5;
    const int lane = tid & 31;
    const int q    = blockIdx.x * 8 + wid;

    const float4* X4 = (const float4*)(X + (size_t)q * DD);
    float4 xr[8];
#pragma unroll
    for (int i = 0; i < 8; ++i) xr[i] = X4[i * 32 + lane];
    const float x2 = g_x2[q];

#pragma unroll 1
    for (int c = 0; c < NCAND; ++c) {
        const int id = g_cand[(size_t)q * NCAND + c];
        const float4* C4 = (const float4*)(C + (size_t)id * DD);
        float s = 0.f;
#pragma unroll
        for (int i = 0; i < 8; ++i) {
            float4 cv = C4[i * 32 + lane];
            s += xr[i].x * cv.x + xr[i].y * cv.y + xr[i].z * cv.z + xr[i].w * cv.w;
        }
#pragma unroll
        for (int o = 16; o > 0; o >>= 1) s += __shfl_xor_sync(0xffffffffu, s, o);
        if (lane == 0) {
            sv[wid][c] = -(fmaf(-2.f, s, x2) + g_c2[id]);   // reference formula order
            si[wid][c] = id;
        }
    }
    __syncwarp();

    if (lane == 0) {
        const float NEG_INF = __int_as_float(0xff800000);
        float v0 = NEG_INF, v1 = NEG_INF, v2 = NEG_INF, v3 = NEG_INF;
        float v4 = NEG_INF, v5 = NEG_INF, v6 = NEG_INF, v7 = NEG_INF;
        int j0 = 0x7FFFFFFF, j1 = 0x7FFFFFFF, j2 = 0x7FFFFFFF, j3 = 0x7FFFFFFF;
        int j4 = 0x7FFFFFFF, j5 = 0x7FFFFFFF, j6 = 0x7FFFFFFF, j7 = 0x7FFFFFFF;
#pragma unroll 1
        for (int c = 0; c < NCAND; ++c) {
            float s = sv[wid][c];
            int   n = si[wid][c];
            TRYINS(s, n)
        }
        sel[wid][0] = j0; sel[wid][1] = j1; sel[wid][2] = j2; sel[wid][3] = j3;
        sel[wid][4] = j4; sel[wid][5] = j5; sel[wid][6] = j6; sel[wid][7] = j7;
        if (out_ids) {
            float* o = out_ids + (size_t)q * KSEL;
            o[0] = (float)j0; o[1] = (float)j1; o[2] = (float)j2; o[3] = (float)j3;
            o[4] = (float)j4; o[5] = (float)j5; o[6] = (float)j6; o[7] = (float)j7;
        }
    }
    __syncwarp();

    const float4* P0 = (const float4*)(C + (size_t)sel[wid][0] * DD);
    const float4* P1 = (const float4*)(C + (size_t)sel[wid][1] * DD);
    const float4* P2 = (const float4*)(C + (size_t)sel[wid][2] * DD);
    const float4* P3 = (const float4*)(C + (size_t)sel[wid][3] * DD);
    const float4* P4 = (const float4*)(C + (size_t)sel[wid][4] * DD);
    const float4* P5 = (const float4*)(C + (size_t)sel[wid][5] * DD);
    const float4* P6 = (const float4*)(C + (size_t)sel[wid][6] * DD);
    const float4* P7 = (const float4*)(C + (size_t)sel[wid][7] * DD);
    float4* O4 = (float4*)(out + (size_t)q * DD);
#pragma unroll
    for (int i = 0; i < 8; ++i) {
        const int f = i * 32 + lane;
        float4 a0 = P0[f], a1 = P1[f], a2 = P2[f], a3 = P3[f];
        float4 a4 = P4[f], a5 = P5[f], a6 = P6[f], a7 = P7[f];
        float4 rr;
        rr.x = (a0.x + a1.x + a2.x + a3.x + a4.x + a5.x + a6.x + a7.x) * 0.125f;
        rr.y = (a0.y + a1.y + a2.y + a3.y + a4.y + a5.y + a6.y + a7.y) * 0.125f;
        rr.z = (a0.z + a1.z + a2.z + a3.z + a4.z + a5.z + a6.z + a7.z) * 0.125f;
        rr.w = (a0.w + a1.w + a2.w + a3.w + a4.w + a5.w + a6.w + a7.w) * 0.125f;
        O4[f] = rr;
    }
}

// ---------------------------------------------------------------------------
extern "C" void kernel_launch(void* const* d_in, const int* in_sizes, int n_in,
                              void* d_out, int out_size)
{
    const float* X = (const float*)d_in[0];   // inputs   [4,2048,1024] f32
    const float* C = (const float*)d_in[1];   // codebook [16384,1024] f32

    float* out     = (float*)d_out;
    float* out_ids = nullptr;
    if (out_size >= MQ * DD + MQ * KSEL)
        out_ids = out + (size_t)MQ * DD;

    cprep_kernel<<<NC / 8, 256>>>(C);   // bf16 convert + c2 norms, one pass
    xprep_kernel<<<MQ / 8, 256>>>(X);   // bf16 convert + x2 norms, one pass

    cudaFuncSetAttribute(shortlist_kernel,
                         cudaFuncAttributeMaxDynamicSharedMemorySize, SMEM_BYTES);
    dim3 grid(MQ / BM, NSPLIT);
    shortlist_kernel<<<grid, NT, SMEM_BYTES>>>();

    rescore_kernel<<<MQ / 8, 256>>>(X, C, out, out_ids);
}

// round 12
// speedup vs baseline: 7.9621x; 1.0795x over previous
#include <cuda_runtime.h>
#include <cuda_bf16.h>
#include <stdint.h>

// Problem dims
#define MQ    8192
#define DD    1024
#define NC    16384
#define KSEL  8
#define NCAND 64

// Shortlist GEMM tiling: 64 queries x 128-code chunks, warp tile 32x32,
// 256 CTAs at occupancy 2 (fills all 148 SMs, 4 warps/SMSP).
#define BM 64
#define BN 128
#define BK 32
#define NT 256
#define NSPLIT 2
#define CODES_PER_CTA (NC / NSPLIT)      // 8192
#define NCHUNK (CODES_PER_CTA / BN)      // 64
#define NKT    (DD / BK)                 // 32

#define A_BYTES 5120u                    // 64 x 40 bf16
#define B_BYTES 10240u                   // 128 x 40 bf16
#define STAGE_BYTES (A_BYTES + B_BYTES)  // 15360
#define NSTAGE 3
#define STG_OFF (NSTAGE * STAGE_BYTES)   // 46080
#define SMEM_BYTES (STG_OFF + BM * BN * 4)  // 46080 + 32768 = 78848

// ---------------------------------------------------------------------------
__device__ float            g_c2[NC];
__device__ float            g_x2[MQ];
__device__ __nv_bfloat16    g_Xh[(size_t)MQ * DD];
__device__ __nv_bfloat16    g_Ch[(size_t)NC * DD];
__device__ int              g_cand[(size_t)MQ * NCAND];

// ---------------------------------------------------------------------------
// Fused convert(bf16) + squared-norm kernels: one warp per row, single pass.
__global__ void cprep_kernel(const float* __restrict__ src) {
    int row = blockIdx.x * 8 + (threadIdx.x >> 5);
    if (row >= NC) return;
    int lane = threadIdx.x & 31;
    const float4* r4 = (const float4*)(src + (size_t)row * DD);
    uint2* dst = (uint2*)(g_Ch + (size_t)row * DD);
    float s = 0.f;
#pragma unroll
    for (int i = 0; i < 8; ++i) {
        float4 v = r4[i * 32 + lane];
        s += v.x * v.x + v.y * v.y + v.z * v.z + v.w * v.w;
        __nv_bfloat162 lo = __floats2bfloat162_rn(v.x, v.y);
        __nv_bfloat162 hi = __floats2bfloat162_rn(v.z, v.w);
        uint2 u;
        u.x = *(uint32_t*)&lo;
        u.y = *(uint32_t*)&hi;
        dst[i * 32 + lane] = u;
    }
#pragma unroll
    for (int o = 16; o > 0; o >>= 1) s += __shfl_xor_sync(0xffffffffu, s, o);
    if (lane == 0) g_c2[row] = s;
}

__global__ void xprep_kernel(const float* __restrict__ src) {
    int row = blockIdx.x * 8 + (threadIdx.x >> 5);
    if (row >= MQ) return;
    int lane = threadIdx.x & 31;
    const float4* r4 = (const float4*)(src + (size_t)row * DD);
    uint2* dst = (uint2*)(g_Xh + (size_t)row * DD);
    float s = 0.f;
#pragma unroll
    for (int i = 0; i < 8; ++i) {
        float4 v = r4[i * 32 + lane];
        s += v.x * v.x + v.y * v.y + v.z * v.z + v.w * v.w;
        __nv_bfloat162 lo = __floats2bfloat162_rn(v.x, v.y);
        __nv_bfloat162 hi = __floats2bfloat162_rn(v.z, v.w);
        uint2 u;
        u.x = *(uint32_t*)&lo;
        u.y = *(uint32_t*)&hi;
        dst[i * 32 + lane] = u;
    }
#pragma unroll
    for (int o = 16; o > 0; o >>= 1) s += __shfl_xor_sync(0xffffffffu, s, o);
    if (lane == 0) g_x2[row] = s;
}

// ---------------------------------------------------------------------------
// Scalar top-8 (value desc; ties -> smaller index first, matching JAX top_k)
#define BUBBLE(va, ia, vb, ib)                                    \
    if (va > vb || (va == vb && ia < ib)) {                       \
        float _tv = va; va = vb; vb = _tv;                        \
        int   _ti = ia; ia = ib; ib = _ti;                        \
    }
#define TRYINS(s, n)                                              \
    if ((s) > v7 || ((s) == v7 && (n) < j7)) {                    \
        v7 = (s); j7 = (n);                                       \
        BUBBLE(v7, j7, v6, j6)                                    \
        BUBBLE(v6, j6, v5, j5)                                    \
        BUBBLE(v5, j5, v4, j4)                                    \
        BUBBLE(v4, j4, v3, j3)                                    \
        BUBBLE(v3, j3, v2, j2)                                    \
        BUBBLE(v2, j2, v1, j1)                                    \
        BUBBLE(v1, j1, v0, j0)                                    \
    }

// ---------------------------------------------------------------------------
// PTX wrappers
__device__ __forceinline__ void ldsm_x4(uint32_t* r, uint32_t addr) {
    asm volatile("ldmatrix.sync.aligned.m8n8.x4.shared.b16 {%0,%1,%2,%3}, [%4];\n"
        : "=r"(r[0]), "=r"(r[1]), "=r"(r[2]), "=r"(r[3]) : "r"(addr));
}
__device__ __forceinline__ void mma_bf16(float* d, const uint32_t* a, const uint32_t* b) {
    asm volatile("mma.sync.aligned.m16n8k16.row.col.f32.bf16.bf16.f32 "
        "{%0,%1,%2,%3}, {%4,%5,%6,%7}, {%8,%9}, {%0,%1,%2,%3};\n"
        : "+f"(d[0]), "+f"(d[1]), "+f"(d[2]), "+f"(d[3])
        : "r"(a[0]), "r"(a[1]), "r"(a[2]), "r"(a[3]), "r"(b[0]), "r"(b[1]));
}
#define CPA(dst, src) \
    asm volatile("cp.async.cg.shared.global [%0], [%1], 16;\n" :: "r"(dst), "l"(src))
#define CP_COMMIT asm volatile("cp.async.commit_group;\n" ::)
#define CP_WAIT1  asm volatile("cp.async.wait_group 1;\n" ::)
#define CP_WAIT0  asm volatile("cp.async.wait_group 0;\n" ::)

// ---------------------------------------------------------------------------
// Shortlist kernel: bf16 mma.sync GEMM (score = 2*xc - c2) + per-thread top-8.
// 3-stage cp.async pipeline, ONE __syncthreads per K-step, occupancy 2.
__global__ void __launch_bounds__(NT, 2) shortlist_kernel() {
    extern __shared__ __align__(128) unsigned char sraw[];
    float* Stg = (float*)(sraw + STG_OFF);

    const int tid  = threadIdx.x;
    const int lane = tid & 31;
    const int wid  = tid >> 5;
    const int wm   = (wid >> 2) * 32;               // warp m-origin: 0,32
    const int wn   = (wid & 3) * 32;                // warp n-origin: 0,32,64,96
    const int gid  = lane >> 2;
    const int tig  = lane & 3;
    const int mBase = blockIdx.x * BM;
    const int cBase = blockIdx.y * CODES_PER_CTA;

    const uint32_t sBase = (uint32_t)__cvta_generic_to_shared(sraw);

    // cp.async decomposition: A 64 rows x 4 segs (1/thread), B 128 rows x 4 segs (2/thread)
    const int a_row = tid >> 2, a_seg = tid & 3;
    const int b_row = tid >> 1, b_seg = (tid & 1) * 2;
    const __nv_bfloat16* aSrc = g_Xh + (size_t)(mBase + a_row) * DD + a_seg * 8;
    const uint32_t aDst = sBase + (uint32_t)(a_row * 40 + a_seg * 8) * 2;
    const uint32_t bDst = sBase + A_BYTES + (uint32_t)(b_row * 40 + b_seg * 8) * 2;

    // ldmatrix lane->address maps
    const int aLdRow = lane & 15;
    const int aLdCol = 8 * (lane >> 4);
    const int bLdRow = (lane & 7) + ((lane >> 4) << 3);
    const int bLdCol = ((lane >> 3) & 1) * 8;

    const float NEG_INF = __int_as_float(0xff800000);
    float v0 = NEG_INF, v1 = NEG_INF, v2 = NEG_INF, v3 = NEG_INF;
    float v4 = NEG_INF, v5 = NEG_INF, v6 = NEG_INF, v7 = NEG_INF;
    int j0 = 0x7FFFFFFF, j1 = 0x7FFFFFFF, j2 = 0x7FFFFFFF, j3 = 0x7FFFFFFF;
    int j4 = 0x7FFFFFFF, j5 = 0x7FFFFFFF, j6 = 0x7FFFFFFF, j7 = 0x7FFFFFFF;

    const int q_scan = tid >> 2;                    // query row (0..63)
    const int l4     = tid & 3;                     // 32-col slice
    const int rot    = (q_scan + l4 * 8) & 31;

    // PF: prefetch K-slab KT of the current chunk's A/B into stage buffer BUF.
#define PF(SRC, KT, BUF)                                                      \
    do {                                                                      \
        uint32_t so = (uint32_t)(BUF) * STAGE_BYTES;                          \
        CPA(aDst + so,       (const void*)(aSrc + (KT) * BK));                \
        CPA(bDst + so,       (const void*)((SRC) + (KT) * BK));               \
        CPA(bDst + so + 16u, (const void*)((SRC) + (KT) * BK + 8));           \
        CP_COMMIT;                                                            \
    } while (0)

    const __nv_bfloat16* bSrc =
        g_Ch + (size_t)(cBase + b_row) * DD + b_seg * 8;

    // chunk-0 prologue: stages 0,1 -> bufs 0,1
    PF(bSrc, 0, 0);
    PF(bSrc, 1, 1);

#pragma unroll 1
    for (int chunk = 0; chunk < NCHUNK; ++chunk) {
        const int nBase = chunk * BN;

        float ac[2][4][4];
#pragma unroll
        for (int ma = 0; ma < 2; ++ma)
#pragma unroll
            for (int nb = 0; nb < 4; ++nb)
#pragma unroll
                for (int r = 0; r < 4; ++r) ac[ma][nb][r] = 0.f;

#pragma unroll 1
        for (int kt = 0; kt < NKT; ++kt) {
            if (kt < NKT - 1) { CP_WAIT1; } else { CP_WAIT0; }
            __syncthreads();
            if (kt + 2 < NKT) PF(bSrc, kt + 2, (kt + 2) % NSTAGE);

            const uint32_t sA = sBase + (uint32_t)(kt % NSTAGE) * STAGE_BYTES;
            const uint32_t sB = sA + A_BYTES;
#pragma unroll
            for (int ks = 0; ks < 2; ++ks) {
                const int k0 = ks * 16;
                uint32_t af[2][4], bf[4][2];
#pragma unroll
                for (int ma = 0; ma < 2; ++ma)
                    ldsm_x4(af[ma],
                            sA + (uint32_t)((wm + ma * 16 + aLdRow) * 40 + k0 + aLdCol) * 2);
#pragma unroll
                for (int nq = 0; nq < 2; ++nq) {
                    uint32_t t[4];
                    ldsm_x4(t, sB + (uint32_t)((wn + nq * 16 + bLdRow) * 40 + k0 + bLdCol) * 2);
                    bf[nq * 2][0] = t[0]; bf[nq * 2][1] = t[1];
                    bf[nq * 2 + 1][0] = t[2]; bf[nq * 2 + 1][1] = t[3];
                }
#pragma unroll
                for (int ma = 0; ma < 2; ++ma)
#pragma unroll
                    for (int nb = 0; nb < 4; ++nb)
                        mma_bf16(ac[ma][nb], af[ma], bf[nb]);
            }
        }
        // After the kt=NKT-1 top-sync, the buf for stage (NKT-3) (== buf0 mod 3)
        // is fully consumed -> safe for next chunk's stage 0 now; stage-1 buf
        // frees after the staging sync below.

        const __nv_bfloat16* bNext =
            g_Ch + (size_t)(cBase + nBase + BN + b_row) * DD + b_seg * 8;
        if (chunk + 1 < NCHUNK) PF(bNext, 0, 0);

        // Stage scores psi = 2*dot - c2 into Stg (separate memory).
#pragma unroll
        for (int ma = 0; ma < 2; ++ma) {
            const int m0 = wm + ma * 16 + gid;
#pragma unroll
            for (int nb = 0; nb < 4; ++nb) {
                const int n0 = wn + nb * 8 + 2 * tig;
                const float cc0 = g_c2[cBase + nBase + n0];
                const float cc1 = g_c2[cBase + nBase + n0 + 1];
                Stg[m0 * BN + n0]           = fmaf(2.f, ac[ma][nb][0], -cc0);
                Stg[m0 * BN + n0 + 1]       = fmaf(2.f, ac[ma][nb][1], -cc1);
                Stg[(m0 + 8) * BN + n0]     = fmaf(2.f, ac[ma][nb][2], -cc0);
                Stg[(m0 + 8) * BN + n0 + 1] = fmaf(2.f, ac[ma][nb][3], -cc1);
            }
        }
        __syncthreads();                            // staging visible; buf1 free
        if (chunk + 1 < NCHUNK) PF(bNext, 1, 1);

        // Top-8 scan: 4 threads per query, 32 cols each (rotated), overlapped
        // with the in-flight prefetches.
#pragma unroll 1
        for (int j = 0; j < 32; ++j) {
            int jj  = (j + rot) & 31;
            int col = l4 * 32 + jj;
            float s = Stg[q_scan * BN + col];
            int   n = cBase + nBase + col;
            TRYINS(s, n)
        }
        __syncthreads();                            // Stg reusable next chunk
        bSrc = bNext;
    }
#undef PF

    // Write 32 candidate ids per (query, split): 4 threads x 8 each.
    int* dst = &g_cand[(size_t)(mBase + q_scan) * NCAND + blockIdx.y * 32 + l4 * 8];
    dst[0] = j0; dst[1] = j1; dst[2] = j2; dst[3] = j3;
    dst[4] = j4; dst[5] = j5; dst[6] = j6; dst[7] = j7;
}

// ---------------------------------------------------------------------------
// Exact fp32 rescore of 64 candidates/query + top-8 + gather/mean.
__global__ void __launch_bounds__(256) rescore_kernel(const float* __restrict__ X,
                                                      const float* __restrict__ C,
                                                      float* __restrict__ out,
                                                      float* __restrict__ out_ids)
{
    __shared__ float sv[8][NCAND];
    __shared__ int   si[8][NCAND];
    __shared__ int   sel[8][KSEL];

    const int tid  = threadIdx.x;
    const int wid  = tid >> 5;
    const int lane = tid & 31;
    const int q    = blockIdx.x * 8 + wid;

    const float4* X4 = (const float4*)(X + (size_t)q * DD);
    float4 xr[8];
#pragma unroll
    for (int i = 0; i < 8; ++i) xr[i] = X4[i * 32 + lane];
    const float x2 = g_x2[q];

#pragma unroll 1
    for (int c = 0; c < NCAND; ++c) {
        const int id = g_cand[(size_t)q * NCAND + c];
        const float4* C4 = (const float4*)(C + (size_t)id * DD);
        float s = 0.f;
#pragma unroll
        for (int i = 0; i < 8; ++i) {
            float4 cv = C4[i * 32 + lane];
            s += xr[i].x * cv.x + xr[i].y * cv.y + xr[i].z * cv.z + xr[i].w * cv.w;
        }
#pragma unroll
        for (int o = 16; o > 0; o >>= 1) s += __shfl_xor_sync(0xffffffffu, s, o);
        if (lane == 0) {
            sv[wid][c] = -(fmaf(-2.f, s, x2) + g_c2[id]);   // reference formula order
            si[wid][c] = id;
        }
    }
    __syncwarp();

    if (lane == 0) {
        const float NEG_INF = __int_as_float(0xff800000);
        float v0 = NEG_INF, v1 = NEG_INF, v2 = NEG_INF, v3 = NEG_INF;
        float v4 = NEG_INF, v5 = NEG_INF, v6 = NEG_INF, v7 = NEG_INF;
        int j0 = 0x7FFFFFFF, j1 = 0x7FFFFFFF, j2 = 0x7FFFFFFF, j3 = 0x7FFFFFFF;
        int j4 = 0x7FFFFFFF, j5 = 0x7FFFFFFF, j6 = 0x7FFFFFFF, j7 = 0x7FFFFFFF;
#pragma unroll 1
        for (int c = 0; c < NCAND; ++c) {
            float s = sv[wid][c];
            int   n = si[wid][c];
            TRYINS(s, n)
        }
        sel[wid][0] = j0; sel[wid][1] = j1; sel[wid][2] = j2; sel[wid][3] = j3;
        sel[wid][4] = j4; sel[wid][5] = j5; sel[wid][6] = j6; sel[wid][7] = j7;
        if (out_ids) {
            float* o = out_ids + (size_t)q * KSEL;
            o[0] = (float)j0; o[1] = (float)j1; o[2] = (float)j2; o[3] = (float)j3;
            o[4] = (float)j4; o[5] = (float)j5; o[6] = (float)j6; o[7] = (float)j7;
        }
    }
    __syncwarp();

    const float4* P0 = (const float4*)(C + (size_t)sel[wid][0] * DD);
    const float4* P1 = (const float4*)(C + (size_t)sel[wid][1] * DD);
    const float4* P2 = (const float4*)(C + (size_t)sel[wid][2] * DD);
    const float4* P3 = (const float4*)(C + (size_t)sel[wid][3] * DD);
    const float4* P4 = (const float4*)(C + (size_t)sel[wid][4] * DD);
    const float4* P5 = (const float4*)(C + (size_t)sel[wid][5] * DD);
    const float4* P6 = (const float4*)(C + (size_t)sel[wid][6] * DD);
    const float4* P7 = (const float4*)(C + (size_t)sel[wid][7] * DD);
    float4* O4 = (float4*)(out + (size_t)q * DD);
#pragma unroll
    for (int i = 0; i < 8; ++i) {
        const int f = i * 32 + lane;
        float4 a0 = P0[f], a1 = P1[f], a2 = P2[f], a3 = P3[f];
        float4 a4 = P4[f], a5 = P5[f], a6 = P6[f], a7 = P7[f];
        float4 rr;
        rr.x = (a0.x + a1.x + a2.x + a3.x + a4.x + a5.x + a6.x + a7.x) * 0.125f;
        rr.y = (a0.y + a1.y + a2.y + a3.y + a4.y + a5.y + a6.y + a7.y) * 0.125f;
        rr.z = (a0.z + a1.z + a2.z + a3.z + a4.z + a5.z + a6.z + a7.z) * 0.125f;
        rr.w = (a0.w + a1.w + a2.w + a3.w + a4.w + a5.w + a6.w + a7.w) * 0.125f;
        O4[f] = rr;
    }
}

// ---------------------------------------------------------------------------
extern "C" void kernel_launch(void* const* d_in, const int* in_sizes, int n_in,
                              void* d_out, int out_size)
{
    const float* X = (const float*)d_in[0];   // inputs   [4,2048,1024] f32
    const float* C = (const float*)d_in[1];   // codebook [16384,1024] f32

    float* out     = (float*)d_out;
    float* out_ids = nullptr;
    if (out_size >= MQ * DD + MQ * KSEL)
        out_ids = out + (size_t)MQ * DD;

    cprep_kernel<<<NC / 8, 256>>>(C);   // bf16 convert + c2 norms, one pass
    xprep_kernel<<<MQ / 8, 256>>>(X);   // bf16 convert + x2 norms, one pass

    cudaFuncSetAttribute(shortlist_kernel,
                         cudaFuncAttributeMaxDynamicSharedMemorySize, SMEM_BYTES);
    dim3 grid(MQ / BM, NSPLIT);
    shortlist_kernel<<<grid, NT, SMEM_BYTES>>>();

    rescore_kernel<<<MQ / 8, 256>>>(X, C, out, out_ids);
}

// round 14
// speedup vs baseline: 9.0406x; 1.1354x over previous
#include <cuda_runtime.h>
#include <cuda_bf16.h>
#include <cuda_fp8.h>
#include <stdint.h>

// Problem dims
#define MQ    8192
#define DD    1024
#define NC    16384
#define KSEL  8
#define NCAND 128

// FP8 shortlist tiling: 64 queries x 128-code chunks, warp tile 32x32,
// K-slab = 64 fp8 bytes, flattened slab pipeline, occupancy 2.
#define BM 64
#define BN 128
#define NT 256
#define NSPLIT 4
#define CODES_PER_CTA (NC / NSPLIT)      // 4096
#define NCHUNK (CODES_PER_CTA / BN)      // 32
#define NKT    16                        // 1024 / 64
#define TOTSLAB (NCHUNK * NKT)           // 512

#define ROWB   80u                       // 64 data bytes + 16 pad
#define A_BYTES (64u * ROWB)             // 5120
#define B_BYTES (128u * ROWB)            // 10240
#define STAGE_BYTES (A_BYTES + B_BYTES)  // 15360
#define NSTAGE 3
#define STG_OFF (NSTAGE * STAGE_BYTES)   // 46080
#define SMEM_BYTES (STG_OFF + BM * BN * 4)  // 78848

// ---------------------------------------------------------------------------
__device__ float    g_c2[NC];
__device__ float    g_x2[MQ];
__device__ uint8_t  g_X8[(size_t)MQ * DD];   // e4m3 queries  (8 MB)
__device__ uint8_t  g_C8[(size_t)NC * DD];   // e4m3 codebook (16 MB)
__device__ int      g_cand[(size_t)MQ * NCAND];

// ---------------------------------------------------------------------------
// Fused convert(e4m3) + squared-norm kernels: one warp per row, single pass.
__device__ __forceinline__ uint32_t pack_fp8x4(float4 v) {
    uint32_t b0 = __nv_cvt_float_to_fp8(v.x, __NV_SATFINITE, __NV_E4M3);
    uint32_t b1 = __nv_cvt_float_to_fp8(v.y, __NV_SATFINITE, __NV_E4M3);
    uint32_t b2 = __nv_cvt_float_to_fp8(v.z, __NV_SATFINITE, __NV_E4M3);
    uint32_t b3 = __nv_cvt_float_to_fp8(v.w, __NV_SATFINITE, __NV_E4M3);
    return b0 | (b1 << 8) | (b2 << 16) | (b3 << 24);
}

__global__ void cprep_kernel(const float* __restrict__ src) {
    int row = blockIdx.x * 8 + (threadIdx.x >> 5);
    if (row >= NC) return;
    int lane = threadIdx.x & 31;
    const float4* r4 = (const float4*)(src + (size_t)row * DD);
    uint32_t* dst = (uint32_t*)(g_C8 + (size_t)row * DD);
    float s = 0.f;
#pragma unroll
    for (int i = 0; i < 8; ++i) {
        float4 v = r4[i * 32 + lane];
        s += v.x * v.x + v.y * v.y + v.z * v.z + v.w * v.w;
        dst[i * 32 + lane] = pack_fp8x4(v);
    }
#pragma unroll
    for (int o = 16; o > 0; o >>= 1) s += __shfl_xor_sync(0xffffffffu, s, o);
    if (lane == 0) g_c2[row] = s;
}

__global__ void xprep_kernel(const float* __restrict__ src) {
    int row = blockIdx.x * 8 + (threadIdx.x >> 5);
    if (row >= MQ) return;
    int lane = threadIdx.x & 31;
    const float4* r4 = (const float4*)(src + (size_t)row * DD);
    uint32_t* dst = (uint32_t*)(g_X8 + (size_t)row * DD);
    float s = 0.f;
#pragma unroll
    for (int i = 0; i < 8; ++i) {
        float4 v = r4[i * 32 + lane];
        s += v.x * v.x + v.y * v.y + v.z * v.z + v.w * v.w;
        dst[i * 32 + lane] = pack_fp8x4(v);
    }
#pragma unroll
    for (int o = 16; o > 0; o >>= 1) s += __shfl_xor_sync(0xffffffffu, s, o);
    if (lane == 0) g_x2[row] = s;
}

// ---------------------------------------------------------------------------
// Scalar top-8 (value desc; ties -> smaller index first, matching JAX top_k)
#define BUBBLE(va, ia, vb, ib)                                    \
    if (va > vb || (va == vb && ia < ib)) {                       \
        float _tv = va; va = vb; vb = _tv;                        \
        int   _ti = ia; ia = ib; ib = _ti;                        \
    }
#define TRYINS(s, n)                                              \
    if ((s) > v7 || ((s) == v7 && (n) < j7)) {                    \
        v7 = (s); j7 = (n);                                       \
        BUBBLE(v7, j7, v6, j6)                                    \
        BUBBLE(v6, j6, v5, j5)                                    \
        BUBBLE(v5, j5, v4, j4)                                    \
        BUBBLE(v4, j4, v3, j3)                                    \
        BUBBLE(v3, j3, v2, j2)                                    \
        BUBBLE(v2, j2, v1, j1)                                    \
        BUBBLE(v1, j1, v0, j0)                                    \
    }

// ---------------------------------------------------------------------------
// PTX wrappers
__device__ __forceinline__ void ldsm_x4(uint32_t* r, uint32_t addr) {
    asm volatile("ldmatrix.sync.aligned.m8n8.x4.shared.b16 {%0,%1,%2,%3}, [%4];\n"
        : "=r"(r[0]), "=r"(r[1]), "=r"(r[2]), "=r"(r[3]) : "r"(addr));
}
__device__ __forceinline__ void mma_fp8(float* d, const uint32_t* a, const uint32_t* b) {
    asm volatile("mma.sync.aligned.m16n8k32.row.col.f32.e4m3.e4m3.f32 "
        "{%0,%1,%2,%3}, {%4,%5,%6,%7}, {%8,%9}, {%0,%1,%2,%3};\n"
        : "+f"(d[0]), "+f"(d[1]), "+f"(d[2]), "+f"(d[3])
        : "r"(a[0]), "r"(a[1]), "r"(a[2]), "r"(a[3]), "r"(b[0]), "r"(b[1]));
}
#define CPA(dst, src) \
    asm volatile("cp.async.cg.shared.global [%0], [%1], 16;\n" :: "r"(dst), "l"(src))
#define CP_COMMIT asm volatile("cp.async.commit_group;\n" ::)
#define CP_WAIT1  asm volatile("cp.async.wait_group 1;\n" ::)
#define CP_WAIT0  asm volatile("cp.async.wait_group 0;\n" ::)

// ---------------------------------------------------------------------------
// Shortlist kernel: e4m3 mma.sync GEMM (score = 2*xc - c2) + per-thread top-8.
// Flattened slab pipeline: global slab counter, prefetch g+2, buf = g%3 --
// the cp.async pipeline never drains, even across chunk boundaries.
__global__ void __launch_bounds__(NT, 2) shortlist_kernel() {
    extern __shared__ __align__(128) unsigned char sraw[];
    float* Stg = (float*)(sraw + STG_OFF);

    const int tid  = threadIdx.x;
    const int lane = tid & 31;
    const int wid  = tid >> 5;
    const int wm   = (wid >> 2) * 32;               // warp m-origin: 0,32
    const int wn   = (wid & 3) * 32;                // warp n-origin: 0,32,64,96
    const int gid  = lane >> 2;
    const int tig  = lane & 3;
    const int mBase = blockIdx.x * BM;
    const int cBase = blockIdx.y * CODES_PER_CTA;

    const uint32_t sBase = (uint32_t)__cvta_generic_to_shared(sraw);

    // cp.async decomposition: A 64 rows x 4 segs (1/thread), B 128 rows x 4 segs (2/thread)
    const int a_row = tid >> 2, a_seg = tid & 3;
    const int b_row = tid >> 1, b_seg = (tid & 1) * 2;
    const uint8_t* aSrc = g_X8 + (size_t)(mBase + a_row) * DD + a_seg * 16;
    const uint8_t* bBase = g_C8 + (size_t)(cBase + b_row) * DD + b_seg * 16;
    const uint32_t aDst = sBase + (uint32_t)a_row * ROWB + a_seg * 16;
    const uint32_t bDst = sBase + A_BYTES + (uint32_t)b_row * ROWB + b_seg * 16;

    // ldmatrix lane->address maps (byte units; rows are 80B apart)
    const int aLdRow = lane & 15;
    const int aLdCol = 16 * (lane >> 4);
    const int bLdRow = (lane & 7) + ((lane >> 4) << 3);
    const int bLdCol = 16 * ((lane >> 3) & 1);

    const float NEG_INF = __int_as_float(0xff800000);
    float v0 = NEG_INF, v1 = NEG_INF, v2 = NEG_INF, v3 = NEG_INF;
    float v4 = NEG_INF, v5 = NEG_INF, v6 = NEG_INF, v7 = NEG_INF;
    int j0 = 0x7FFFFFFF, j1 = 0x7FFFFFFF, j2 = 0x7FFFFFFF, j3 = 0x7FFFFFFF;
    int j4 = 0x7FFFFFFF, j5 = 0x7FFFFFFF, j6 = 0x7FFFFFFF, j7 = 0x7FFFFFFF;

    const int q_scan = tid >> 2;                    // query row (0..63)
    const int l4     = tid & 3;                     // 32-col slice
    const int rot    = (q_scan + l4 * 8) & 31;

    // PF: prefetch slab G (chunk G/NKT, kt G%NKT) into buf G%3.
    // B rows advance by BN per chunk (DD bytes per row, fp8).
#define PF(G)                                                                 \
    do {                                                                      \
        uint32_t so = (uint32_t)((G) % NSTAGE) * STAGE_BYTES;                 \
        const uint8_t* as = aSrc + ((G) & (NKT - 1)) * 64;                    \
        const uint8_t* bs = bBase + (size_t)((G) >> 4) * (BN * DD)            \
                            + ((G) & (NKT - 1)) * 64;                         \
        CPA(aDst + so, as);                                                   \
        CPA(bDst + so, bs);                                                   \
        CPA(bDst + so + 16u, bs + 16);                                        \
        CP_COMMIT;                                                            \
    } while (0)

    PF(0);
    PF(1);

    float ac[2][4][4];
#pragma unroll
    for (int ma = 0; ma < 2; ++ma)
#pragma unroll
        for (int nb = 0; nb < 4; ++nb)
#pragma unroll
            for (int r = 0; r < 4; ++r) ac[ma][nb][r] = 0.f;

#pragma unroll 1
    for (int g = 0; g < TOTSLAB; ++g) {
        if (g < TOTSLAB - 1) { CP_WAIT1; } else { CP_WAIT0; }
        __syncthreads();                 // slab g ready; buf (g+2)%3 consumed
        if (g + 2 < TOTSLAB) PF(g + 2);

        const uint32_t sA = sBase + (uint32_t)(g % NSTAGE) * STAGE_BYTES;
        const uint32_t sB = sA + A_BYTES;
#pragma unroll
        for (int ks = 0; ks < 2; ++ks) {          // two k32 steps per 64B slab
            const int k0 = ks * 32;
            uint32_t af[2][4], bf[4][2];
#pragma unroll
            for (int ma = 0; ma < 2; ++ma)
                ldsm_x4(af[ma],
                        sA + (uint32_t)(wm + ma * 16 + aLdRow) * ROWB + k0 + aLdCol);
#pragma unroll
            for (int nq = 0; nq < 2; ++nq) {
                uint32_t t[4];
                ldsm_x4(t, sB + (uint32_t)(wn + nq * 16 + bLdRow) * ROWB + k0 + bLdCol);
                bf[nq * 2][0] = t[0]; bf[nq * 2][1] = t[1];
                bf[nq * 2 + 1][0] = t[2]; bf[nq * 2 + 1][1] = t[3];
            }
#pragma unroll
            for (int ma = 0; ma < 2; ++ma)
#pragma unroll
                for (int nb = 0; nb < 4; ++nb)
                    mma_fp8(ac[ma][nb], af[ma], bf[nb]);
        }

        if ((g & (NKT - 1)) == NKT - 1) {
            // ---- chunk epilogue (pipeline stays full: slabs g+1,g+2 in flight)
            const int nBase = (g >> 4) * BN;

            // Stage scores psi = 2*dot - c2 into Stg.
#pragma unroll
            for (int ma = 0; ma < 2; ++ma) {
                const int m0 = wm + ma * 16 + gid;
#pragma unroll
                for (int nb = 0; nb < 4; ++nb) {
                    const int n0 = wn + nb * 8 + 2 * tig;
                    const float cc0 = g_c2[cBase + nBase + n0];
                    const float cc1 = g_c2[cBase + nBase + n0 + 1];
                    Stg[m0 * BN + n0]           = fmaf(2.f, ac[ma][nb][0], -cc0);
                    Stg[m0 * BN + n0 + 1]       = fmaf(2.f, ac[ma][nb][1], -cc1);
                    Stg[(m0 + 8) * BN + n0]     = fmaf(2.f, ac[ma][nb][2], -cc0);
                    Stg[(m0 + 8) * BN + n0 + 1] = fmaf(2.f, ac[ma][nb][3], -cc1);
                }
            }
            __syncthreads();

            // Top-8 scan: 4 threads per query, 32 cols each (rotated).
            // (No trailing sync: next write to Stg is 16 slabs away, behind
            // multiple __syncthreads.)
#pragma unroll 1
            for (int j = 0; j < 32; ++j) {
                int jj  = (j + rot) & 31;
                int col = l4 * 32 + jj;
                float s = Stg[q_scan * BN + col];
                int   n = cBase + nBase + col;
                TRYINS(s, n)
            }

            // reset accumulators for next chunk
#pragma unroll
            for (int ma = 0; ma < 2; ++ma)
#pragma unroll
                for (int nb = 0; nb < 4; ++nb)
#pragma unroll
                    for (int r = 0; r < 4; ++r) ac[ma][nb][r] = 0.f;
        }
    }
#undef PF

    // Write 32 candidate ids per (query, split): 4 threads x 8 each.
    int* dst = &g_cand[(size_t)(mBase + q_scan) * NCAND + blockIdx.y * 32 + l4 * 8];
    dst[0] = j0; dst[1] = j1; dst[2] = j2; dst[3] = j3;
    dst[4] = j4; dst[5] = j5; dst[6] = j6; dst[7] = j7;
}

// ---------------------------------------------------------------------------
// Exact fp32 rescore of 128 candidates/query + top-8 + gather/mean.
__global__ void __launch_bounds__(256) rescore_kernel(const float* __restrict__ X,
                                                      const float* __restrict__ C,
                                                      float* __restrict__ out,
                                                      float* __restrict__ out_ids)
{
    __shared__ float sv[8][NCAND];
    __shared__ int   si[8][NCAND];
    __shared__ int   sel[8][KSEL];

    const int tid  = threadIdx.x;
    const int wid  = tid >> 5;
    const int lane = tid & 31;
    const int q    = blockIdx.x * 8 + wid;

    const float4* X4 = (const float4*)(X + (size_t)q * DD);
    float4 xr[8];
#pragma unroll
    for (int i = 0; i < 8; ++i) xr[i] = X4[i * 32 + lane];
    const float x2 = g_x2[q];

#pragma unroll 1
    for (int c = 0; c < NCAND; ++c) {
        const int id = g_cand[(size_t)q * NCAND + c];
        const float4* C4 = (const float4*)(C + (size_t)id * DD);
        float s = 0.f;
#pragma unroll
        for (int i = 0; i < 8; ++i) {
            float4 cv = C4[i * 32 + lane];
            s += xr[i].x * cv.x + xr[i].y * cv.y + xr[i].z * cv.z + xr[i].w * cv.w;
        }
#pragma unroll
        for (int o = 16; o > 0; o >>= 1) s += __shfl_xor_sync(0xffffffffu, s, o);
        if (lane == 0) {
            sv[wid][c] = -(fmaf(-2.f, s, x2) + g_c2[id]);   // reference formula order
            si[wid][c] = id;
        }
    }
    __syncwarp();

    if (lane == 0) {
        const float NEG_INF = __int_as_float(0xff800000);
        float v0 = NEG_INF, v1 = NEG_INF, v2 = NEG_INF, v3 = NEG_INF;
        float v4 = NEG_INF, v5 = NEG_INF, v6 = NEG_INF, v7 = NEG_INF;
        int j0 = 0x7FFFFFFF, j1 = 0x7FFFFFFF, j2 = 0x7FFFFFFF, j3 = 0x7FFFFFFF;
        int j4 = 0x7FFFFFFF, j5 = 0x7FFFFFFF, j6 = 0x7FFFFFFF, j7 = 0x7FFFFFFF;
#pragma unroll 1
        for (int c = 0; c < NCAND; ++c) {
            float s = sv[wid][c];
            int   n = si[wid][c];
            TRYINS(s, n)
        }
        sel[wid][0] = j0; sel[wid][1] = j1; sel[wid][2] = j2; sel[wid][3] = j3;
        sel[wid][4] = j4; sel[wid][5] = j5; sel[wid][6] = j6; sel[wid][7] = j7;
        if (out_ids) {
            float* o = out_ids + (size_t)q * KSEL;
            o[0] = (float)j0; o[1] = (float)j1; o[2] = (float)j2; o[3] = (float)j3;
            o[4] = (float)j4; o[5] = (float)j5; o[6] = (float)j6; o[7] = (float)j7;
        }
    }
    __syncwarp();

    const float4* P0 = (const float4*)(C + (size_t)sel[wid][0] * DD);
    const float4* P1 = (const float4*)(C + (size_t)sel[wid][1] * DD);
    const float4* P2 = (const float4*)(C + (size_t)sel[wid][2] * DD);
    const float4* P3 = (const float4*)(C + (size_t)sel[wid][3] * DD);
    const float4* P4 = (const float4*)(C + (size_t)sel[wid][4] * DD);
    const float4* P5 = (const float4*)(C + (size_t)sel[wid][5] * DD);
    const float4* P6 = (const float4*)(C + (size_t)sel[wid][6] * DD);
    const float4* P7 = (const float4*)(C + (size_t)sel[wid][7] * DD);
    float4* O4 = (float4*)(out + (size_t)q * DD);
#pragma unroll
    for (int i = 0; i < 8; ++i) {
        const int f = i * 32 + lane;
        float4 a0 = P0[f], a1 = P1[f], a2 = P2[f], a3 = P3[f];
        float4 a4 = P4[f], a5 = P5[f], a6 = P6[f], a7 = P7[f];
        float4 rr;
        rr.x = (a0.x + a1.x + a2.x + a3.x + a4.x + a5.x + a6.x + a7.x) * 0.125f;
        rr.y = (a0.y + a1.y + a2.y + a3.y + a4.y + a5.y + a6.y + a7.y) * 0.125f;
        rr.z = (a0.z + a1.z + a2.z + a3.z + a4.z + a5.z + a6.z + a7.z) * 0.125f;
        rr.w = (a0.w + a1.w + a2.w + a3.w + a4.w + a5.w + a6.w + a7.w) * 0.125f;
        O4[f] = rr;
    }
}

// ---------------------------------------------------------------------------
extern "C" void kernel_launch(void* const* d_in, const int* in_sizes, int n_in,
                              void* d_out, int out_size)
{
    const float* X = (const float*)d_in[0];   // inputs   [4,2048,1024] f32
    const float* C = (const float*)d_in[1];   // codebook [16384,1024] f32

    float* out     = (float*)d_out;
    float* out_ids = nullptr;
    if (out_size >= MQ * DD + MQ * KSEL)
        out_ids = out + (size_t)MQ * DD;

    cprep_kernel<<<NC / 8, 256>>>(C);   // e4m3 convert + c2 norms, one pass
    xprep_kernel<<<MQ / 8, 256>>>(X);   // e4m3 convert + x2 norms, one pass

    cudaFuncSetAttribute(shortlist_kernel,
                         cudaFuncAttributeMaxDynamicSharedMemorySize, SMEM_BYTES);
    dim3 grid(MQ / BM, NSPLIT);
    shortlist_kernel<<<grid, NT, SMEM_BYTES>>>();

    rescore_kernel<<<MQ / 8, 256>>>(X, C, out, out_ids);
}